// round 11
// baseline (speedup 1.0000x reference)
#include <cuda_runtime.h>
#include <cuda_fp16.h>
#include <cstdint>

// Problem constants (fixed shapes)
constexpr int N_NODES = 8192;
constexpr int D = 512;
constexpr int E_EDGES = 131072;
constexpr int B_GR = 16;
constexpr int NPG = 512;
constexpr int S_SEL = 128;
constexpr int L_LAYERS = 3;

// dense GEMM tiling (R7-proven shape)
constexpr int BM = 128;
constexpr int BN = 128;
constexpr int BK = 64;             // k-chunk (64 halfs = 128 B/row)
constexpr int NCH = D / BK;        // 8 chunks
constexpr int NMAT = 11;

// dense smem stage: padded rows of 144B; A tile + W tile per stage
constexpr int ROWB = 144;
constexpr int SA = 0;                    // 128*144 = 18432
constexpr int SW = 18432;
constexpr int STAGE = 36864;
constexpr int NSTG = 3;
constexpr int SMEM_GEMM = NSTG * STAGE;  // 110592

// fused edge kernel smem layout (BM_E = 64 edges/CTA, 2 CTAs/SM)
constexpr int BME = 64;
constexpr int ZROWB = 1040;                        // 512 halfs + 16B pad (260 w ≡ 4 mod 32)
constexpr int EZ_BYTES = BME * ZROWB;              // 66560
constexpr int EW_OFF = EZ_BYTES;
constexpr int EW_STAGE = 128 * ROWB;               // 18432 (W: 128 n-rows x 64 k-halfs)
constexpr int EDG_IDX = EW_OFF + 2 * EW_STAGE;     // 103424 (sDst, 256 B)
constexpr int SMEM_EDGE = EDG_IDX + 256;           // 103680 -> 2 CTAs/SM

// -------- static device scratch --------
__device__ float    g_x[N_NODES * D];
__device__ unsigned g_agg[N_NODES * D];
__device__ __align__(16) __half g_h16[N_NODES * D];        // LN output (fp16)
__device__ __align__(16) __half g_t16[N_NODES * D];        // FFN intermediate (fp16)
__device__ __align__(16) __half g_A16[N_NODES * D];        // A = H@Wd + b1 (fp16)
__device__ __align__(16) __half g_B16[N_NODES * D];        // B = H@Wb (fp16)
__device__ __align__(16) __half g_W16[(size_t)NMAT * D * D];
__device__ float    g_out[N_NODES * D];                    // final pre-gather output

// ---------------- helpers ----------------
__device__ __forceinline__ unsigned fenc(float f) {
    unsigned b = __float_as_uint(f);
    return (b & 0x80000000u) ? ~b : (b | 0x80000000u);
}
__device__ __forceinline__ float fdec(unsigned u) {
    unsigned b = (u & 0x80000000u) ? (u & 0x7fffffffu) : ~u;
    return __uint_as_float(b);
}
__device__ __forceinline__ uint32_t smem_u32(const void* p) {
    uint32_t a;
    asm("{ .reg .u64 t; cvta.to.shared.u64 t, %1; cvt.u32.u64 %0, t; }" : "=r"(a) : "l"(p));
    return a;
}
__device__ __forceinline__ void cp16(uint32_t dst, const void* src) {
    asm volatile("cp.async.cg.shared.global [%0], [%1], 16;" :: "r"(dst), "l"(src) : "memory");
}
__device__ __forceinline__ void cp_commit() {
    asm volatile("cp.async.commit_group;" ::: "memory");
}
template <int N>
__device__ __forceinline__ void cp_wait() {
    asm volatile("cp.async.wait_group %0;" :: "n"(N) : "memory");
}
__device__ __forceinline__ void ldm_x4(uint32_t* r, uint32_t addr) {
    asm volatile("ldmatrix.sync.aligned.m8n8.x4.shared.b16 {%0,%1,%2,%3}, [%4];"
                 : "=r"(r[0]), "=r"(r[1]), "=r"(r[2]), "=r"(r[3]) : "r"(addr));
}
__device__ __forceinline__ void mma_h(float* d, const uint32_t* a, uint32_t b0, uint32_t b1) {
    asm volatile(
        "mma.sync.aligned.m16n8k16.row.col.f32.f16.f16.f32 "
        "{%0,%1,%2,%3}, {%4,%5,%6,%7}, {%8,%9}, {%0,%1,%2,%3};"
        : "+f"(d[0]), "+f"(d[1]), "+f"(d[2]), "+f"(d[3])
        : "r"(a[0]), "r"(a[1]), "r"(a[2]), "r"(a[3]), "r"(b0), "r"(b1));
}
// cp.async a 128-row x 64-half chunk into stage offset (4 iters of 256 threads)
__device__ __forceinline__ void cp_rows128(uint32_t sbase, const __half* base, int k0, int tid) {
    #pragma unroll
    for (int i = 0; i < 4; i++) {
        int tx = tid + i * 256;            // 0..1023
        int row = tx >> 3, seg = tx & 7;
        cp16(sbase + row * ROWB + seg * 16, base + (size_t)row * D + k0 + seg * 8);
    }
}

// ================= init / prep / lnc / gather =================
__global__ void k_init(const float* __restrict__ x) {
    int i = blockIdx.x * 256 + threadIdx.x;
    g_x[i] = x[i];
    g_agg[i] = 0u;
}

// fp16 weight prep: mats 0..8: l=m/3; r0: Wd=W1top-W1bot; r1: Wb=W1bot; r2: W2^T
// mat 9: ffnW1^T ; 10: ffnW2^T.  Image [n][k] row-major fp16.
__global__ void k_prep16(const float* __restrict__ W1, const float* __restrict__ W2,
                         const float* __restrict__ fW1, const float* __restrict__ fW2,
                         __half* __restrict__ img) {
    int m = blockIdx.y;
    int e = blockIdx.x * 256 + threadIdx.x;
    int n = e & 511, k = e >> 9;
    float w;
    if (m < 9) {
        int l = m / 3, r = m % 3;
        const float* base = W1 + (size_t)l * 2 * D * D;
        if (r == 0)      w = base[(size_t)k * D + n] - base[(size_t)(D + k) * D + n];
        else if (r == 1) w = base[(size_t)(D + k) * D + n];
        else             w = W2[((size_t)l * D + k) * D + n];
    } else if (m == 9)   w = fW1[(size_t)k * D + n];
    else                 w = fW2[(size_t)k * D + n];
    img[(size_t)m * D * D + (size_t)n * D + k] = __float2half(w);
}

// fused combine (optional) + LayerNorm -> fp16.
__global__ __launch_bounds__(128) void k_lnc(int useAgg,
                                             const float* __restrict__ b2,
                                             const float* __restrict__ gamma,
                                             const float* __restrict__ beta,
                                             __half* __restrict__ out) {
    __shared__ float red[8];
    int row = blockIdx.x;
    int t = threadIdx.x;
    size_t base = (size_t)row * D + t * 4;
    float4 v = *(const float4*)(g_x + base);
    if (useAgg) {
        uint4 u = *(const uint4*)(g_agg + base);
        *(uint4*)(g_agg + base) = make_uint4(0u, 0u, 0u, 0u);
        float4 bv = ((const float4*)b2)[t];
        float m0 = u.x ? fdec(u.x) + bv.x : 0.f;
        float m1 = u.y ? fdec(u.y) + bv.y : 0.f;
        float m2 = u.z ? fdec(u.z) + bv.z : 0.f;
        float m3 = u.w ? fdec(u.w) + bv.w : 0.f;
        v.x += fmaxf(m0, 0.f); v.y += fmaxf(m1, 0.f);
        v.z += fmaxf(m2, 0.f); v.w += fmaxf(m3, 0.f);
        *(float4*)(g_x + base) = v;
    }
    float s = v.x + v.y + v.z + v.w;
    #pragma unroll
    for (int o = 16; o > 0; o >>= 1) s += __shfl_xor_sync(0xffffffffu, s, o);
    if ((t & 31) == 0) red[t >> 5] = s;
    __syncthreads();
    if (t == 0) red[4] = red[0] + red[1] + red[2] + red[3];
    __syncthreads();
    float mu = red[4] * (1.0f / D);
    __syncthreads();
    float dx = v.x - mu, dy = v.y - mu, dz = v.z - mu, dw = v.w - mu;
    float q = dx * dx + dy * dy + dz * dz + dw * dw;
    #pragma unroll
    for (int o = 16; o > 0; o >>= 1) q += __shfl_xor_sync(0xffffffffu, q, o);
    if ((t & 31) == 0) red[t >> 5] = q;
    __syncthreads();
    if (t == 0) red[4] = red[0] + red[1] + red[2] + red[3];
    __syncthreads();
    float rstd = rsqrtf(red[4] * (1.0f / D) + 1e-5f);
    float4 g4 = ((const float4*)gamma)[t];
    float4 b4 = ((const float4*)beta)[t];
    __half2 h0 = __floats2half2_rn(dx * rstd * g4.x + b4.x, dy * rstd * g4.y + b4.y);
    __half2 h1 = __floats2half2_rn(dz * rstd * g4.z + b4.z, dw * rstd * g4.w + b4.w);
    *(uint2*)(out + base) = make_uint2(*(uint32_t*)&h0, *(uint32_t*)&h1);
}

__global__ __launch_bounds__(128) void k_gather(const float* __restrict__ y,
                                                const int* __restrict__ sel,
                                                float* __restrict__ out) {
    int r = blockIdx.x;
    int b = r >> 7, s = r & (S_SEL - 1);
    int node = b * NPG + sel[b * S_SEL + s];
    ((float4*)(out + (size_t)r * D))[threadIdx.x] =
        ((const float4*)(y + (size_t)node * D))[threadIdx.x];
}

// ================= dense fp16 GEMM (R7 shape): out = op(A16 @ W + bias [+res]) =================
// grid(x = D/128 = 4, y = M/128), 256 threads, 2 CTAs/SM
__global__ __launch_bounds__(256, 2) void k_mma_gemm(
    const __half* __restrict__ Ain,
    const __half* __restrict__ w,
    const float* __restrict__ bias,
    const float* __restrict__ res,
    float* __restrict__ out,
    __half* __restrict__ out16,
    int relu)
{
    extern __shared__ char smem[];
    int tid = threadIdx.x;
    int n0 = blockIdx.x * BN;
    int m0 = blockIdx.y * BM;
    int lane = tid & 31, wm = (tid >> 5) & 1, wn = tid >> 6;

    uint32_t s[NSTG];
    #pragma unroll
    for (int i = 0; i < NSTG; i++) s[i] = smem_u32(smem + i * STAGE);
    const __half* abase = Ain + (size_t)m0 * D;
    const __half* wbase = w + (size_t)n0 * D;
    uint32_t aoff = (uint32_t)(wm * 64 + (lane & 7) + ((lane >> 3) & 1) * 8) * ROWB
                  + ((lane >> 4) & 1) * 16;
    uint32_t boff = (uint32_t)(wn * 32 + (lane & 7) + ((lane >= 16) ? 8 : 0)) * ROWB
                  + ((lane >> 3) & 1) * 16;

    float acc[4][4][4] = {};

    cp_rows128(s[0] + SA, abase, 0, tid);
    cp_rows128(s[0] + SW, wbase, 0, tid);
    cp_commit();
    cp_rows128(s[1] + SA, abase, BK, tid);
    cp_rows128(s[1] + SW, wbase, BK, tid);
    cp_commit();
    cp_wait<1>();
    __syncthreads();

    for (int c = 0; c < NCH; c++) {
        uint32_t sc = s[c % NSTG];
        if (c + 2 < NCH) {
            uint32_t sn = s[(c + 2) % NSTG];
            cp_rows128(sn + SA, abase, (c + 2) * BK, tid);
            cp_rows128(sn + SW, wbase, (c + 2) * BK, tid);
            cp_commit();
        }
        #pragma unroll
        for (int kh = 0; kh < 4; kh++) {
            uint32_t bh[2][4];
            #pragma unroll
            for (int np = 0; np < 2; np++)
                ldm_x4(bh[np], sc + SW + boff + np * 16 * ROWB + kh * 32);
            #pragma unroll
            for (int mf = 0; mf < 4; mf++) {
                uint32_t ah[4];
                ldm_x4(ah, sc + SA + aoff + mf * 16 * ROWB + kh * 32);
                #pragma unroll
                for (int np = 0; np < 2; np++) {
                    #pragma unroll
                    for (int j = 0; j < 2; j++)
                        mma_h(acc[mf][np * 2 + j], ah, bh[np][2 * j], bh[np][2 * j + 1]);
                }
            }
        }
        if (c + 2 < NCH) cp_wait<1>();
        else if (c + 1 < NCH) cp_wait<0>();
        __syncthreads();
    }

    #pragma unroll
    for (int mf = 0; mf < 4; mf++) {
        int r0 = m0 + wm * 64 + mf * 16 + (lane >> 2);
        int colb = n0 + wn * 32 + 2 * (lane & 3);
        #pragma unroll
        for (int nf = 0; nf < 4; nf++) {
            int col = colb + nf * 8;
            float2 bv = bias ? *(const float2*)(bias + col) : make_float2(0.f, 0.f);
            float c0 = acc[mf][nf][0] + bv.x, c1 = acc[mf][nf][1] + bv.y;
            float c2 = acc[mf][nf][2] + bv.x, c3 = acc[mf][nf][3] + bv.y;
            if (relu) {
                c0 = fmaxf(c0, 0.f); c1 = fmaxf(c1, 0.f);
                c2 = fmaxf(c2, 0.f); c3 = fmaxf(c3, 0.f);
            }
            if (res) {
                float2 r1v = *(const float2*)(res + (size_t)r0 * D + col);
                float2 r2v = *(const float2*)(res + (size_t)(r0 + 8) * D + col);
                c0 += r1v.x; c1 += r1v.y; c2 += r2v.x; c3 += r2v.y;
            }
            if (out) {
                *(float2*)(out + (size_t)r0 * D + col) = make_float2(c0, c1);
                *(float2*)(out + (size_t)(r0 + 8) * D + col) = make_float2(c2, c3);
            }
            if (out16) {
                __half2 h0 = __floats2half2_rn(c0, c1);
                __half2 h1 = __floats2half2_rn(c2, c3);
                *(uint32_t*)(out16 + (size_t)r0 * D + col) = *(uint32_t*)&h0;
                *(uint32_t*)(out16 + (size_t)(r0 + 8) * D + col) = *(uint32_t*)&h1;
            }
        }
    }
}

// ================= fused edge kernel v2 (64 edges/CTA, 2 CTAs/SM) =================
// Per CTA: build Z = relu(A16[dst]+B16[src]) (64 x 512 fp16) in smem once,
// then loop 4 N-tiles of W2 (double-buffered cp.async), MMA from smem Z,
// gated atomicMax epilogue per N-tile.
// grid(E/64 = 2048), 256 threads (8 warps: wm = wid&1 -> M 2x32, wn = wid>>1 -> N 4x32)
__global__ __launch_bounds__(256, 2) void k_edge_fused(
    const __half* __restrict__ w16,
    const int* __restrict__ src,
    const int* __restrict__ dst,
    const float* __restrict__ b2,
    unsigned* __restrict__ agg)
{
    extern __shared__ char smem[];
    int tid = threadIdx.x;
    int e0 = blockIdx.x * BME;
    int lane = tid & 31, wm = (tid >> 5) & 1, wn = tid >> 6;

    uint32_t zb = smem_u32(smem);
    uint32_t sw[2];
    sw[0] = smem_u32(smem + EW_OFF);
    sw[1] = smem_u32(smem + EW_OFF + EW_STAGE);
    int* sDst = (int*)(smem + EDG_IDX);
    if (tid < BME) sDst[tid] = dst[e0 + tid];

    // ---- build Z in smem: row = tid>>2 (0..63), 16 x 16B segments per thread ----
    // Each row = 512 halfs = 1024 B = 64 segments; 4 threads/row -> 16 segs each.
    {
        int row = tid >> 2;
        int de = dst[e0 + row], se = src[e0 + row];
        const uint4* arow = (const uint4*)(g_A16 + (size_t)de * D);
        const uint4* brow = (const uint4*)(g_B16 + (size_t)se * D);
        const __half2 zero2 = __floats2half2_rn(0.f, 0.f);
        int sg0 = (tid & 3) * 16;
        #pragma unroll
        for (int s = 0; s < 16; s++) {
            int sg = sg0 + s;
            uint4 av = arow[sg], bv = brow[sg];
            uint4 r;
            __half2 h;
            h = __hmax2(__hadd2(*(__half2*)&av.x, *(__half2*)&bv.x), zero2); r.x = *(uint32_t*)&h;
            h = __hmax2(__hadd2(*(__half2*)&av.y, *(__half2*)&bv.y), zero2); r.y = *(uint32_t*)&h;
            h = __hmax2(__hadd2(*(__half2*)&av.z, *(__half2*)&bv.z), zero2); r.z = *(uint32_t*)&h;
            h = __hmax2(__hadd2(*(__half2*)&av.w, *(__half2*)&bv.w), zero2); r.w = *(uint32_t*)&h;
            *(uint4*)((char*)smem + row * ZROWB + sg * 16) = r;
        }
    }
    __syncthreads();

    uint32_t aoff = (uint32_t)(wm * 32 + (lane & 7) + ((lane >> 3) & 1) * 8) * ZROWB
                  + ((lane >> 4) & 1) * 16;
    uint32_t boff = (uint32_t)(wn * 32 + (lane & 7) + ((lane >= 16) ? 8 : 0)) * ROWB
                  + ((lane >> 3) & 1) * 16;

    for (int nt = 0; nt < 4; nt++) {
        const __half* wbase = w16 + (size_t)(nt * 128) * D;

        // double-buffered W pipeline (1 sync per chunk)
        cp_rows128(sw[0], wbase, 0, tid);
        cp_commit();
        cp_wait<0>();
        __syncthreads();

        float acc[2][4][4] = {};
        for (int c = 0; c < NCH; c++) {
            uint32_t sc = sw[c & 1];
            if (c + 1 < NCH) {
                cp_rows128(sw[(c + 1) & 1], wbase, (c + 1) * BK, tid);
                cp_commit();
            }
            #pragma unroll
            for (int kh = 0; kh < 4; kh++) {
                uint32_t bh[2][4];
                #pragma unroll
                for (int np = 0; np < 2; np++)
                    ldm_x4(bh[np], sc + boff + np * 16 * ROWB + kh * 32);
                #pragma unroll
                for (int mf = 0; mf < 2; mf++) {
                    uint32_t ah[4];
                    ldm_x4(ah, zb + aoff + mf * 16 * ZROWB + c * 128 + kh * 32);
                    #pragma unroll
                    for (int np = 0; np < 2; np++) {
                        #pragma unroll
                        for (int j = 0; j < 2; j++)
                            mma_h(acc[mf][np * 2 + j], ah, bh[np][2 * j], bh[np][2 * j + 1]);
                    }
                }
            }
            if (c + 1 < NCH) cp_wait<0>();
            __syncthreads();
        }

        // gated atomic segment-max for this N-tile
        #pragma unroll
        for (int mf = 0; mf < 2; mf++) {
            int r0 = wm * 32 + mf * 16 + (lane >> 2);
            int colb = nt * 128 + wn * 32 + 2 * (lane & 3);
            unsigned* p0 = agg + (size_t)sDst[r0] * D + colb;
            unsigned* p1 = agg + (size_t)sDst[r0 + 8] * D + colb;
            #pragma unroll
            for (int nf = 0; nf < 4; nf++) {
                float2 bv = *(const float2*)(b2 + colb + nf * 8);
                float t0 = -bv.x, t1 = -bv.y;
                if (acc[mf][nf][0] > t0) atomicMax(p0 + nf * 8,     fenc(acc[mf][nf][0]));
                if (acc[mf][nf][1] > t1) atomicMax(p0 + nf * 8 + 1, fenc(acc[mf][nf][1]));
                if (acc[mf][nf][2] > t0) atomicMax(p1 + nf * 8,     fenc(acc[mf][nf][2]));
                if (acc[mf][nf][3] > t1) atomicMax(p1 + nf * 8 + 1, fenc(acc[mf][nf][3]));
            }
        }
        __syncthreads();   // W stages reused next nt
    }
}

// ================= host launcher =================
extern "C" void kernel_launch(void* const* d_in, const int* in_sizes, int n_in,
                              void* d_out, int out_size) {
    const float* x       = (const float*)d_in[0];
    const int*   eidx    = (const int*)d_in[1];
    const int*   sel     = (const int*)d_in[2];
    const float* conv_W1 = (const float*)d_in[4];
    const float* conv_b1 = (const float*)d_in[5];
    const float* conv_W2 = (const float*)d_in[6];
    const float* conv_b2 = (const float*)d_in[7];
    const float* ln1_g   = (const float*)d_in[8];
    const float* ln1_b   = (const float*)d_in[9];
    const float* ln2_g   = (const float*)d_in[10];
    const float* ln2_b   = (const float*)d_in[11];
    const float* ffn_W1  = (const float*)d_in[12];
    const float* ffn_b1  = (const float*)d_in[13];
    const float* ffn_W2  = (const float*)d_in[14];
    const float* ffn_b2  = (const float*)d_in[15];
    float* out = (float*)d_out;

    const int* src = eidx;
    const int* dst = eidx + E_EDGES;

    float *gx, *gout;
    unsigned* gagg;
    __half *gh16, *gt16, *ga16, *gb16, *gw16;
    cudaGetSymbolAddress((void**)&gx, g_x);
    cudaGetSymbolAddress((void**)&gout, g_out);
    cudaGetSymbolAddress((void**)&gagg, g_agg);
    cudaGetSymbolAddress((void**)&gh16, g_h16);
    cudaGetSymbolAddress((void**)&gt16, g_t16);
    cudaGetSymbolAddress((void**)&ga16, g_A16);
    cudaGetSymbolAddress((void**)&gb16, g_B16);
    cudaGetSymbolAddress((void**)&gw16, g_W16);

    cudaFuncSetAttribute(k_mma_gemm, cudaFuncAttributeMaxDynamicSharedMemorySize, SMEM_GEMM);
    cudaFuncSetAttribute(k_edge_fused, cudaFuncAttributeMaxDynamicSharedMemorySize, SMEM_EDGE);

    auto W = [&](int m) { return gw16 + (size_t)m * D * D; };

    const int ND = N_NODES * D;

    k_init<<<ND / 256, 256>>>(x);
    {
        dim3 grid(1024, NMAT);
        k_prep16<<<grid, 256>>>(conv_W1, conv_W2, ffn_W1, ffn_W2, gw16);
    }

    dim3 ggemm(D / BN, N_NODES / BM);   // (4, 64)

    for (int l = 0; l < L_LAYERS; l++) {
        if (l == 0)
            k_lnc<<<N_NODES, 128>>>(0, conv_b2, ln1_g, ln1_b, gh16);
        else
            k_lnc<<<N_NODES, 128>>>(1, conv_b2 + (size_t)(l - 1) * D, ln1_g, ln1_b, gh16);
        k_mma_gemm<<<ggemm, 256, SMEM_GEMM>>>(gh16, W(l * 3 + 0),
                                              conv_b1 + (size_t)l * D, nullptr,
                                              nullptr, ga16, 0);
        k_mma_gemm<<<ggemm, 256, SMEM_GEMM>>>(gh16, W(l * 3 + 1),
                                              nullptr, nullptr, nullptr, gb16, 0);
        k_edge_fused<<<E_EDGES / BME, 256, SMEM_EDGE>>>(W(l * 3 + 2), src, dst,
                                                        conv_b2 + (size_t)l * D, gagg);
    }

    k_lnc<<<N_NODES, 128>>>(1, conv_b2 + (size_t)2 * D, ln2_g, ln2_b, gh16);
    k_mma_gemm<<<ggemm, 256, SMEM_GEMM>>>(gh16, W(9), ffn_b1, nullptr,
                                          nullptr, gt16, 1);
    k_mma_gemm<<<ggemm, 256, SMEM_GEMM>>>(gt16, W(10), ffn_b2, gx,
                                          gout, nullptr, 0);
    k_gather<<<B_GR * S_SEL, 128>>>(gout, sel, out);
}

// round 12
// speedup vs baseline: 1.2863x; 1.2863x over previous
#include <cuda_runtime.h>
#include <cuda_fp16.h>
#include <cstdint>

// Problem constants (fixed shapes)
constexpr int N_NODES = 8192;
constexpr int D = 512;
constexpr int E_EDGES = 131072;
constexpr int B_GR = 16;
constexpr int NPG = 512;
constexpr int S_SEL = 128;
constexpr int L_LAYERS = 3;

// GEMM tiling (R7-proven shape)
constexpr int BM = 128;
constexpr int BN = 128;
constexpr int BK = 64;             // k-chunk (64 halfs = 128 B/row)
constexpr int NCH = D / BK;        // 8 chunks
constexpr int NMAT = 11;

// smem stage: padded rows of 144B; A tile + W tile per stage
constexpr int ROWB = 144;
constexpr int SA = 0;                    // 128*144 = 18432
constexpr int SW = 18432;
constexpr int STAGE = 36864;
constexpr int NSTG = 3;
constexpr int SM_IDX = NSTG * STAGE;     // edge: sDst (512 B)
constexpr int SMEM_GEMM = NSTG * STAGE;          // 110592
constexpr int SMEM_EDGE = NSTG * STAGE + 512;    // 111104

// -------- static device scratch --------
__device__ float    g_x[N_NODES * D];
__device__ unsigned g_agg[N_NODES * D];
__device__ __align__(16) __half g_h16[N_NODES * D];        // LN output (fp16)
__device__ __align__(16) __half g_t16[N_NODES * D];        // FFN intermediate (fp16)
__device__ __align__(16) __half g_A16[N_NODES * D];        // A = H@Wd + b1 (fp16)
__device__ __align__(16) __half g_B16[N_NODES * D];        // B = H@Wb (fp16)
__device__ __align__(16) __half g_Z[(size_t)E_EDGES * D];  // edge features (fp16)
__device__ __align__(16) __half g_W16[(size_t)NMAT * D * D];
__device__ float    g_out[N_NODES * D];                    // final pre-gather output

// ---------------- helpers ----------------
__device__ __forceinline__ unsigned fenc(float f) {
    unsigned b = __float_as_uint(f);
    return (b & 0x80000000u) ? ~b : (b | 0x80000000u);
}
__device__ __forceinline__ float fdec(unsigned u) {
    unsigned b = (u & 0x80000000u) ? (u & 0x7fffffffu) : ~u;
    return __uint_as_float(b);
}
__device__ __forceinline__ uint32_t smem_u32(const void* p) {
    uint32_t a;
    asm("{ .reg .u64 t; cvta.to.shared.u64 t, %1; cvt.u32.u64 %0, t; }" : "=r"(a) : "l"(p));
    return a;
}
__device__ __forceinline__ void cp16(uint32_t dst, const void* src) {
    asm volatile("cp.async.cg.shared.global [%0], [%1], 16;" :: "r"(dst), "l"(src) : "memory");
}
__device__ __forceinline__ void cp_commit() {
    asm volatile("cp.async.commit_group;" ::: "memory");
}
template <int N>
__device__ __forceinline__ void cp_wait() {
    asm volatile("cp.async.wait_group %0;" :: "n"(N) : "memory");
}
__device__ __forceinline__ void ldm_x4(uint32_t* r, uint32_t addr) {
    asm volatile("ldmatrix.sync.aligned.m8n8.x4.shared.b16 {%0,%1,%2,%3}, [%4];"
                 : "=r"(r[0]), "=r"(r[1]), "=r"(r[2]), "=r"(r[3]) : "r"(addr));
}
__device__ __forceinline__ void mma_h(float* d, const uint32_t* a, uint32_t b0, uint32_t b1) {
    asm volatile(
        "mma.sync.aligned.m16n8k16.row.col.f32.f16.f16.f32 "
        "{%0,%1,%2,%3}, {%4,%5,%6,%7}, {%8,%9}, {%0,%1,%2,%3};"
        : "+f"(d[0]), "+f"(d[1]), "+f"(d[2]), "+f"(d[3])
        : "r"(a[0]), "r"(a[1]), "r"(a[2]), "r"(a[3]), "r"(b0), "r"(b1));
}
// cp.async a 128-row x 64-half chunk into stage offset (4 iters of 256 threads)
__device__ __forceinline__ void cp_rows128(uint32_t sbase, const __half* base, int k0, int tid) {
    #pragma unroll
    for (int i = 0; i < 4; i++) {
        int tx = tid + i * 256;            // 0..1023
        int row = tx >> 3, seg = tx & 7;
        cp16(sbase + row * ROWB + seg * 16, base + (size_t)row * D + k0 + seg * 8);
    }
}

// ================= init / prep / lnc / zbuild / gather =================
__global__ void k_init(const float* __restrict__ x) {
    int i = blockIdx.x * 256 + threadIdx.x;
    g_x[i] = x[i];
    g_agg[i] = 0u;
}

// fp16 weight prep: mats 0..8: l=m/3; r0: Wd=W1top-W1bot; r1: Wb=W1bot; r2: W2^T
// mat 9: ffnW1^T ; 10: ffnW2^T.  Image [n][k] row-major fp16.
// NOTE: Wd (m=l*3) and Wb (m=l*3+1) are contiguous -> single N=1024 GEMM image.
__global__ void k_prep16(const float* __restrict__ W1, const float* __restrict__ W2,
                         const float* __restrict__ fW1, const float* __restrict__ fW2,
                         __half* __restrict__ img) {
    int m = blockIdx.y;
    int e = blockIdx.x * 256 + threadIdx.x;
    int n = e & 511, k = e >> 9;
    float w;
    if (m < 9) {
        int l = m / 3, r = m % 3;
        const float* base = W1 + (size_t)l * 2 * D * D;
        if (r == 0)      w = base[(size_t)k * D + n] - base[(size_t)(D + k) * D + n];
        else if (r == 1) w = base[(size_t)(D + k) * D + n];
        else             w = W2[((size_t)l * D + k) * D + n];
    } else if (m == 9)   w = fW1[(size_t)k * D + n];
    else                 w = fW2[(size_t)k * D + n];
    img[(size_t)m * D * D + (size_t)n * D + k] = __float2half(w);
}

// fused combine (optional) + LayerNorm -> fp16.
__global__ __launch_bounds__(128) void k_lnc(int useAgg,
                                             const float* __restrict__ b2,
                                             const float* __restrict__ gamma,
                                             const float* __restrict__ beta,
                                             __half* __restrict__ out) {
    __shared__ float red[8];
    int row = blockIdx.x;
    int t = threadIdx.x;
    size_t base = (size_t)row * D + t * 4;
    float4 v = *(const float4*)(g_x + base);
    if (useAgg) {
        uint4 u = *(const uint4*)(g_agg + base);
        *(uint4*)(g_agg + base) = make_uint4(0u, 0u, 0u, 0u);
        float4 bv = ((const float4*)b2)[t];
        float m0 = u.x ? fdec(u.x) + bv.x : 0.f;
        float m1 = u.y ? fdec(u.y) + bv.y : 0.f;
        float m2 = u.z ? fdec(u.z) + bv.z : 0.f;
        float m3 = u.w ? fdec(u.w) + bv.w : 0.f;
        v.x += fmaxf(m0, 0.f); v.y += fmaxf(m1, 0.f);
        v.z += fmaxf(m2, 0.f); v.w += fmaxf(m3, 0.f);
        *(float4*)(g_x + base) = v;
    }
    float s = v.x + v.y + v.z + v.w;
    #pragma unroll
    for (int o = 16; o > 0; o >>= 1) s += __shfl_xor_sync(0xffffffffu, s, o);
    if ((t & 31) == 0) red[t >> 5] = s;
    __syncthreads();
    if (t == 0) red[4] = red[0] + red[1] + red[2] + red[3];
    __syncthreads();
    float mu = red[4] * (1.0f / D);
    __syncthreads();
    float dx = v.x - mu, dy = v.y - mu, dz = v.z - mu, dw = v.w - mu;
    float q = dx * dx + dy * dy + dz * dz + dw * dw;
    #pragma unroll
    for (int o = 16; o > 0; o >>= 1) q += __shfl_xor_sync(0xffffffffu, q, o);
    if ((t & 31) == 0) red[t >> 5] = q;
    __syncthreads();
    if (t == 0) red[4] = red[0] + red[1] + red[2] + red[3];
    __syncthreads();
    float rstd = rsqrtf(red[4] * (1.0f / D) + 1e-5f);
    float4 g4 = ((const float4*)gamma)[t];
    float4 b4 = ((const float4*)beta)[t];
    __half2 h0 = __floats2half2_rn(dx * rstd * g4.x + b4.x, dy * rstd * g4.y + b4.y);
    __half2 h1 = __floats2half2_rn(dz * rstd * g4.z + b4.z, dw * rstd * g4.w + b4.w);
    *(uint2*)(out + base) = make_uint2(*(uint32_t*)&h0, *(uint32_t*)&h1);
}

// Z build (fp16 in / fp16 out): Zh[e][k] = relu_h(A16[dst[e]][k] + B16[src[e]][k])
// 8 edges per 256-thread block; each thread handles 2x16B segments of one edge row.
__global__ __launch_bounds__(256) void k_zbuild(const int* __restrict__ src,
                                                const int* __restrict__ dst) {
    int e = blockIdx.x * 8 + (threadIdx.x >> 5);
    int sg = threadIdx.x & 31;
    int de = dst[e], se = src[e];
    const uint4* a = (const uint4*)(g_A16 + (size_t)de * D);
    const uint4* b = (const uint4*)(g_B16 + (size_t)se * D);
    uint4* z = (uint4*)(g_Z + (size_t)e * D);
    const __half2 zero2 = __floats2half2_rn(0.f, 0.f);
    #pragma unroll
    for (int i = 0; i < 2; i++) {
        int s = sg + i * 32;
        uint4 av = a[s], bv = b[s];
        uint4 r;
        __half2 h;
        h = __hmax2(__hadd2(*(__half2*)&av.x, *(__half2*)&bv.x), zero2); r.x = *(uint32_t*)&h;
        h = __hmax2(__hadd2(*(__half2*)&av.y, *(__half2*)&bv.y), zero2); r.y = *(uint32_t*)&h;
        h = __hmax2(__hadd2(*(__half2*)&av.z, *(__half2*)&bv.z), zero2); r.z = *(uint32_t*)&h;
        h = __hmax2(__hadd2(*(__half2*)&av.w, *(__half2*)&bv.w), zero2); r.w = *(uint32_t*)&h;
        z[s] = r;
    }
}

__global__ __launch_bounds__(128) void k_gather(const float* __restrict__ y,
                                                const int* __restrict__ sel,
                                                float* __restrict__ out) {
    int r = blockIdx.x;
    int b = r >> 7, s = r & (S_SEL - 1);
    int node = b * NPG + sel[b * S_SEL + s];
    ((float4*)(out + (size_t)r * D))[threadIdx.x] =
        ((const float4*)(y + (size_t)node * D))[threadIdx.x];
}

// ================= dense fp16 GEMM (generic, R7 shape) =================
// grid(x = D/128 = 4, y = M/128), 256 threads, 2 CTAs/SM
__global__ __launch_bounds__(256, 2) void k_mma_gemm(
    const __half* __restrict__ Ain,
    const __half* __restrict__ w,
    const float* __restrict__ bias,
    const float* __restrict__ res,
    float* __restrict__ out,
    __half* __restrict__ out16,
    int relu)
{
    extern __shared__ char smem[];
    int tid = threadIdx.x;
    int n0 = blockIdx.x * BN;
    int m0 = blockIdx.y * BM;
    int lane = tid & 31, wm = (tid >> 5) & 1, wn = tid >> 6;

    uint32_t s[NSTG];
    #pragma unroll
    for (int i = 0; i < NSTG; i++) s[i] = smem_u32(smem + i * STAGE);
    const __half* abase = Ain + (size_t)m0 * D;
    const __half* wbase = w + (size_t)n0 * D;
    uint32_t aoff = (uint32_t)(wm * 64 + (lane & 7) + ((lane >> 3) & 1) * 8) * ROWB
                  + ((lane >> 4) & 1) * 16;
    uint32_t boff = (uint32_t)(wn * 32 + (lane & 7) + ((lane >= 16) ? 8 : 0)) * ROWB
                  + ((lane >> 3) & 1) * 16;

    float acc[4][4][4] = {};

    cp_rows128(s[0] + SA, abase, 0, tid);
    cp_rows128(s[0] + SW, wbase, 0, tid);
    cp_commit();
    cp_rows128(s[1] + SA, abase, BK, tid);
    cp_rows128(s[1] + SW, wbase, BK, tid);
    cp_commit();
    cp_wait<1>();
    __syncthreads();

    for (int c = 0; c < NCH; c++) {
        uint32_t sc = s[c % NSTG];
        if (c + 2 < NCH) {
            uint32_t sn = s[(c + 2) % NSTG];
            cp_rows128(sn + SA, abase, (c + 2) * BK, tid);
            cp_rows128(sn + SW, wbase, (c + 2) * BK, tid);
            cp_commit();
        }
        #pragma unroll
        for (int kh = 0; kh < 4; kh++) {
            uint32_t bh[2][4];
            #pragma unroll
            for (int np = 0; np < 2; np++)
                ldm_x4(bh[np], sc + SW + boff + np * 16 * ROWB + kh * 32);
            #pragma unroll
            for (int mf = 0; mf < 4; mf++) {
                uint32_t ah[4];
                ldm_x4(ah, sc + SA + aoff + mf * 16 * ROWB + kh * 32);
                #pragma unroll
                for (int np = 0; np < 2; np++) {
                    #pragma unroll
                    for (int j = 0; j < 2; j++)
                        mma_h(acc[mf][np * 2 + j], ah, bh[np][2 * j], bh[np][2 * j + 1]);
                }
            }
        }
        if (c + 2 < NCH) cp_wait<1>();
        else if (c + 1 < NCH) cp_wait<0>();
        __syncthreads();
    }

    #pragma unroll
    for (int mf = 0; mf < 4; mf++) {
        int r0 = m0 + wm * 64 + mf * 16 + (lane >> 2);
        int colb = n0 + wn * 32 + 2 * (lane & 3);
        #pragma unroll
        for (int nf = 0; nf < 4; nf++) {
            int col = colb + nf * 8;
            float2 bv = bias ? *(const float2*)(bias + col) : make_float2(0.f, 0.f);
            float c0 = acc[mf][nf][0] + bv.x, c1 = acc[mf][nf][1] + bv.y;
            float c2 = acc[mf][nf][2] + bv.x, c3 = acc[mf][nf][3] + bv.y;
            if (relu) {
                c0 = fmaxf(c0, 0.f); c1 = fmaxf(c1, 0.f);
                c2 = fmaxf(c2, 0.f); c3 = fmaxf(c3, 0.f);
            }
            if (res) {
                float2 r1v = *(const float2*)(res + (size_t)r0 * D + col);
                float2 r2v = *(const float2*)(res + (size_t)(r0 + 8) * D + col);
                c0 += r1v.x; c1 += r1v.y; c2 += r2v.x; c3 += r2v.y;
            }
            if (out) {
                *(float2*)(out + (size_t)r0 * D + col) = make_float2(c0, c1);
                *(float2*)(out + (size_t)(r0 + 8) * D + col) = make_float2(c2, c3);
            }
            if (out16) {
                __half2 h0 = __floats2half2_rn(c0, c1);
                __half2 h1 = __floats2half2_rn(c2, c3);
                *(uint32_t*)(out16 + (size_t)r0 * D + col) = *(uint32_t*)&h0;
                *(uint32_t*)(out16 + (size_t)(r0 + 8) * D + col) = *(uint32_t*)&h1;
            }
        }
    }
}

// ================= merged A|B node GEMM =================
// w is the combined [1024 x 512] image (Wd rows 0..511, Wb rows 512..1023).
// grid(x = 1024/128 = 8, y = M/128). blockIdx.x < 4 -> A (bias b1), else -> B.
__global__ __launch_bounds__(256, 2) void k_mma_ab(
    const __half* __restrict__ Hm,
    const __half* __restrict__ w,
    const float* __restrict__ b1,
    __half* __restrict__ A16,
    __half* __restrict__ B16)
{
    extern __shared__ char smem[];
    int tid = threadIdx.x;
    int n0 = blockIdx.x * BN;          // 0..896
    int m0 = blockIdx.y * BM;
    int lane = tid & 31, wm = (tid >> 5) & 1, wn = tid >> 6;

    bool isA = (n0 < D);
    __half* dstbuf = isA ? A16 : B16;
    int cbase = isA ? 0 : D;
    const float* bias = isA ? b1 : nullptr;

    uint32_t s[NSTG];
    #pragma unroll
    for (int i = 0; i < NSTG; i++) s[i] = smem_u32(smem + i * STAGE);
    const __half* abase = Hm + (size_t)m0 * D;
    const __half* wbase = w + (size_t)n0 * D;
    uint32_t aoff = (uint32_t)(wm * 64 + (lane & 7) + ((lane >> 3) & 1) * 8) * ROWB
                  + ((lane >> 4) & 1) * 16;
    uint32_t boff = (uint32_t)(wn * 32 + (lane & 7) + ((lane >= 16) ? 8 : 0)) * ROWB
                  + ((lane >> 3) & 1) * 16;

    float acc[4][4][4] = {};

    cp_rows128(s[0] + SA, abase, 0, tid);
    cp_rows128(s[0] + SW, wbase, 0, tid);
    cp_commit();
    cp_rows128(s[1] + SA, abase, BK, tid);
    cp_rows128(s[1] + SW, wbase, BK, tid);
    cp_commit();
    cp_wait<1>();
    __syncthreads();

    for (int c = 0; c < NCH; c++) {
        uint32_t sc = s[c % NSTG];
        if (c + 2 < NCH) {
            uint32_t sn = s[(c + 2) % NSTG];
            cp_rows128(sn + SA, abase, (c + 2) * BK, tid);
            cp_rows128(sn + SW, wbase, (c + 2) * BK, tid);
            cp_commit();
        }
        #pragma unroll
        for (int kh = 0; kh < 4; kh++) {
            uint32_t bh[2][4];
            #pragma unroll
            for (int np = 0; np < 2; np++)
                ldm_x4(bh[np], sc + SW + boff + np * 16 * ROWB + kh * 32);
            #pragma unroll
            for (int mf = 0; mf < 4; mf++) {
                uint32_t ah[4];
                ldm_x4(ah, sc + SA + aoff + mf * 16 * ROWB + kh * 32);
                #pragma unroll
                for (int np = 0; np < 2; np++) {
                    #pragma unroll
                    for (int j = 0; j < 2; j++)
                        mma_h(acc[mf][np * 2 + j], ah, bh[np][2 * j], bh[np][2 * j + 1]);
                }
            }
        }
        if (c + 2 < NCH) cp_wait<1>();
        else if (c + 1 < NCH) cp_wait<0>();
        __syncthreads();
    }

    #pragma unroll
    for (int mf = 0; mf < 4; mf++) {
        int r0 = m0 + wm * 64 + mf * 16 + (lane >> 2);
        int colb = n0 + wn * 32 + 2 * (lane & 3);
        #pragma unroll
        for (int nf = 0; nf < 4; nf++) {
            int col = colb + nf * 8;
            float2 bv = bias ? *(const float2*)(bias + col) : make_float2(0.f, 0.f);
            float c0 = acc[mf][nf][0] + bv.x, c1 = acc[mf][nf][1] + bv.y;
            float c2 = acc[mf][nf][2] + bv.x, c3 = acc[mf][nf][3] + bv.y;
            int dc = col - cbase;
            __half2 h0 = __floats2half2_rn(c0, c1);
            __half2 h1 = __floats2half2_rn(c2, c3);
            *(uint32_t*)(dstbuf + (size_t)r0 * D + dc) = *(uint32_t*)&h0;
            *(uint32_t*)(dstbuf + (size_t)(r0 + 8) * D + dc) = *(uint32_t*)&h1;
        }
    }
}

// ================= edge GEMM (R7 shape): Zh @ W2h -> gated atomicMax =================
// grid(x = D/128 = 4, y = E/128 = 1024), 256 threads, 2 CTAs/SM
__global__ __launch_bounds__(256, 2) void k_mma_edge(
    const __half* __restrict__ w16,
    const int* __restrict__ dst,
    const float* __restrict__ b2,
    unsigned* __restrict__ agg)
{
    extern __shared__ char smem[];
    int tid = threadIdx.x;
    int n0 = blockIdx.x * BN;
    int e0 = blockIdx.y * BM;
    int lane = tid & 31, wm = (tid >> 5) & 1, wn = tid >> 6;

    int* sDst = (int*)(smem + SM_IDX);
    if (tid < 128) sDst[tid] = dst[e0 + tid];

    uint32_t s[NSTG];
    #pragma unroll
    for (int i = 0; i < NSTG; i++) s[i] = smem_u32(smem + i * STAGE);
    const __half* abase = g_Z + (size_t)e0 * D;
    const __half* wbase = w16 + (size_t)n0 * D;
    uint32_t aoff = (uint32_t)(wm * 64 + (lane & 7) + ((lane >> 3) & 1) * 8) * ROWB
                  + ((lane >> 4) & 1) * 16;
    uint32_t boff = (uint32_t)(wn * 32 + (lane & 7) + ((lane >= 16) ? 8 : 0)) * ROWB
                  + ((lane >> 3) & 1) * 16;

    float acc[4][4][4] = {};

    cp_rows128(s[0] + SA, abase, 0, tid);
    cp_rows128(s[0] + SW, wbase, 0, tid);
    cp_commit();
    cp_rows128(s[1] + SA, abase, BK, tid);
    cp_rows128(s[1] + SW, wbase, BK, tid);
    cp_commit();
    cp_wait<1>();
    __syncthreads();

    for (int c = 0; c < NCH; c++) {
        uint32_t sc = s[c % NSTG];
        if (c + 2 < NCH) {
            uint32_t sn = s[(c + 2) % NSTG];
            cp_rows128(sn + SA, abase, (c + 2) * BK, tid);
            cp_rows128(sn + SW, wbase, (c + 2) * BK, tid);
            cp_commit();
        }
        #pragma unroll
        for (int kh = 0; kh < 4; kh++) {
            uint32_t bh[2][4];
            #pragma unroll
            for (int np = 0; np < 2; np++)
                ldm_x4(bh[np], sc + SW + boff + np * 16 * ROWB + kh * 32);
            #pragma unroll
            for (int mf = 0; mf < 4; mf++) {
                uint32_t ah[4];
                ldm_x4(ah, sc + SA + aoff + mf * 16 * ROWB + kh * 32);
                #pragma unroll
                for (int np = 0; np < 2; np++) {
                    #pragma unroll
                    for (int j = 0; j < 2; j++)
                        mma_h(acc[mf][np * 2 + j], ah, bh[np][2 * j], bh[np][2 * j + 1]);
                }
            }
        }
        if (c + 2 < NCH) cp_wait<1>();
        else if (c + 1 < NCH) cp_wait<0>();
        __syncthreads();
    }

    // gated atomic segment-max (v + b2 <= 0 can never affect relu(max+b2))
    #pragma unroll
    for (int mf = 0; mf < 4; mf++) {
        int r0 = wm * 64 + mf * 16 + (lane >> 2);
        int colb = n0 + wn * 32 + 2 * (lane & 3);
        unsigned* p0 = agg + (size_t)sDst[r0] * D + colb;
        unsigned* p1 = agg + (size_t)sDst[r0 + 8] * D + colb;
        #pragma unroll
        for (int nf = 0; nf < 4; nf++) {
            float2 bv = *(const float2*)(b2 + colb + nf * 8);
            float t0 = -bv.x, t1 = -bv.y;
            if (acc[mf][nf][0] > t0) atomicMax(p0 + nf * 8,     fenc(acc[mf][nf][0]));
            if (acc[mf][nf][1] > t1) atomicMax(p0 + nf * 8 + 1, fenc(acc[mf][nf][1]));
            if (acc[mf][nf][2] > t0) atomicMax(p1 + nf * 8,     fenc(acc[mf][nf][2]));
            if (acc[mf][nf][3] > t1) atomicMax(p1 + nf * 8 + 1, fenc(acc[mf][nf][3]));
        }
    }
}

// ================= host launcher =================
extern "C" void kernel_launch(void* const* d_in, const int* in_sizes, int n_in,
                              void* d_out, int out_size) {
    const float* x       = (const float*)d_in[0];
    const int*   eidx    = (const int*)d_in[1];
    const int*   sel     = (const int*)d_in[2];
    const float* conv_W1 = (const float*)d_in[4];
    const float* conv_b1 = (const float*)d_in[5];
    const float* conv_W2 = (const float*)d_in[6];
    const float* conv_b2 = (const float*)d_in[7];
    const float* ln1_g   = (const float*)d_in[8];
    const float* ln1_b   = (const float*)d_in[9];
    const float* ln2_g   = (const float*)d_in[10];
    const float* ln2_b   = (const float*)d_in[11];
    const float* ffn_W1  = (const float*)d_in[12];
    const float* ffn_b1  = (const float*)d_in[13];
    const float* ffn_W2  = (const float*)d_in[14];
    const float* ffn_b2  = (const float*)d_in[15];
    float* out = (float*)d_out;

    const int* src = eidx;
    const int* dst = eidx + E_EDGES;

    float *gx, *gout;
    unsigned* gagg;
    __half *gh16, *gt16, *ga16, *gb16, *gw16;
    cudaGetSymbolAddress((void**)&gx, g_x);
    cudaGetSymbolAddress((void**)&gout, g_out);
    cudaGetSymbolAddress((void**)&gagg, g_agg);
    cudaGetSymbolAddress((void**)&gh16, g_h16);
    cudaGetSymbolAddress((void**)&gt16, g_t16);
    cudaGetSymbolAddress((void**)&ga16, g_A16);
    cudaGetSymbolAddress((void**)&gb16, g_B16);
    cudaGetSymbolAddress((void**)&gw16, g_W16);

    cudaFuncSetAttribute(k_mma_gemm, cudaFuncAttributeMaxDynamicSharedMemorySize, SMEM_GEMM);
    cudaFuncSetAttribute(k_mma_ab,   cudaFuncAttributeMaxDynamicSharedMemorySize, SMEM_GEMM);
    cudaFuncSetAttribute(k_mma_edge, cudaFuncAttributeMaxDynamicSharedMemorySize, SMEM_EDGE);

    auto W = [&](int m) { return gw16 + (size_t)m * D * D; };

    const int ND = N_NODES * D;

    k_init<<<ND / 256, 256>>>(x);
    {
        dim3 grid(1024, NMAT);
        k_prep16<<<grid, 256>>>(conv_W1, conv_W2, ffn_W1, ffn_W2, gw16);
    }

    dim3 ggemm(D / BN, N_NODES / BM);        // (4, 64)
    dim3 gab(2 * D / BN, N_NODES / BM);      // (8, 64) merged A|B
    dim3 gedge(D / BN, E_EDGES / BM);        // (4, 1024)

    for (int l = 0; l < L_LAYERS; l++) {
        if (l == 0)
            k_lnc<<<N_NODES, 128>>>(0, conv_b2, ln1_g, ln1_b, gh16);
        else
            k_lnc<<<N_NODES, 128>>>(1, conv_b2 + (size_t)(l - 1) * D, ln1_g, ln1_b, gh16);
        k_mma_ab<<<gab, 256, SMEM_GEMM>>>(gh16, W(l * 3 + 0),
                                          conv_b1 + (size_t)l * D, ga16, gb16);
        k_zbuild<<<E_EDGES / 8, 256>>>(src, dst);
        k_mma_edge<<<gedge, 256, SMEM_EDGE>>>(W(l * 3 + 2), dst,
                                              conv_b2 + (size_t)l * D, gagg);
    }

    k_lnc<<<N_NODES, 128>>>(1, conv_b2 + (size_t)2 * D, ln2_g, ln2_b, gh16);
    k_mma_gemm<<<ggemm, 256, SMEM_GEMM>>>(gh16, W(9), ffn_b1, nullptr,
                                          nullptr, gt16, 1);
    k_mma_gemm<<<ggemm, 256, SMEM_GEMM>>>(gt16, W(10), ffn_b2, gx,
                                          gout, nullptr, 0);
    k_gather<<<B_GR * S_SEL, 128>>>(gout, sel, out);
}

// round 13
// speedup vs baseline: 1.3255x; 1.0305x over previous
#include <cuda_runtime.h>
#include <cuda_fp16.h>
#include <cstdint>
#include <cfloat>

// Problem constants (fixed shapes)
constexpr int N_NODES = 8192;
constexpr int D = 512;
constexpr int E_EDGES = 131072;
constexpr int B_GR = 16;
constexpr int NPG = 512;
constexpr int S_SEL = 128;
constexpr int L_LAYERS = 3;

// GEMM tiling (R7-proven shape)
constexpr int BM = 128;
constexpr int BN = 128;
constexpr int BK = 64;             // k-chunk (64 halfs = 128 B/row)
constexpr int NCH = D / BK;        // 8 chunks
constexpr int NMAT = 11;

// smem stage: padded rows of 144B; A tile + W tile per stage
constexpr int ROWB = 144;
constexpr int SA = 0;                    // 128*144 = 18432
constexpr int SW = 18432;
constexpr int STAGE = 36864;
constexpr int NSTG = 3;
constexpr int SM_IDX = NSTG * STAGE;     // edge: sDst (512 B)
constexpr int SMEM_GEMM = NSTG * STAGE;          // 110592
constexpr int SMEM_EDGE = NSTG * STAGE + 512;    // 111104
constexpr int TPAD = 132;                // f32 epilogue tile row stride (words)

// -------- static device scratch --------
__device__ float    g_x[N_NODES * D];
__device__ unsigned g_agg[N_NODES * D];
__device__ __align__(16) __half g_h16[N_NODES * D];        // LN output (fp16)
__device__ __align__(16) __half g_t16[N_NODES * D];        // FFN intermediate (fp16)
__device__ __align__(16) __half g_A16[N_NODES * D];        // A = H@Wd + b1 (fp16)
__device__ __align__(16) __half g_B16[N_NODES * D];        // B = H@Wb (fp16)
__device__ __align__(16) __half g_Z[(size_t)E_EDGES * D];  // edge features (sorted, fp16)
__device__ __align__(16) __half g_W16[(size_t)NMAT * D * D];
__device__ float    g_out[N_NODES * D];                    // final pre-gather output
// edge sort-by-dst scratch
__device__ int g_cnt[N_NODES];     // histogram
__device__ int g_cur[N_NODES];     // scatter cursors
__device__ int g_eDst[E_EDGES];    // sorted dst
__device__ int g_eSrc[E_EDGES];    // sorted src

// ---------------- helpers ----------------
__device__ __forceinline__ unsigned fenc(float f) {
    unsigned b = __float_as_uint(f);
    return (b & 0x80000000u) ? ~b : (b | 0x80000000u);
}
__device__ __forceinline__ float fdec(unsigned u) {
    unsigned b = (u & 0x80000000u) ? (u & 0x7fffffffu) : ~u;
    return __uint_as_float(b);
}
__device__ __forceinline__ uint32_t smem_u32(const void* p) {
    uint32_t a;
    asm("{ .reg .u64 t; cvta.to.shared.u64 t, %1; cvt.u32.u64 %0, t; }" : "=r"(a) : "l"(p));
    return a;
}
__device__ __forceinline__ void cp16(uint32_t dst, const void* src) {
    asm volatile("cp.async.cg.shared.global [%0], [%1], 16;" :: "r"(dst), "l"(src) : "memory");
}
__device__ __forceinline__ void cp_commit() {
    asm volatile("cp.async.commit_group;" ::: "memory");
}
template <int N>
__device__ __forceinline__ void cp_wait() {
    asm volatile("cp.async.wait_group %0;" :: "n"(N) : "memory");
}
__device__ __forceinline__ void ldm_x4(uint32_t* r, uint32_t addr) {
    asm volatile("ldmatrix.sync.aligned.m8n8.x4.shared.b16 {%0,%1,%2,%3}, [%4];"
                 : "=r"(r[0]), "=r"(r[1]), "=r"(r[2]), "=r"(r[3]) : "r"(addr));
}
__device__ __forceinline__ void mma_h(float* d, const uint32_t* a, uint32_t b0, uint32_t b1) {
    asm volatile(
        "mma.sync.aligned.m16n8k16.row.col.f32.f16.f16.f32 "
        "{%0,%1,%2,%3}, {%4,%5,%6,%7}, {%8,%9}, {%0,%1,%2,%3};"
        : "+f"(d[0]), "+f"(d[1]), "+f"(d[2]), "+f"(d[3])
        : "r"(a[0]), "r"(a[1]), "r"(a[2]), "r"(a[3]), "r"(b0), "r"(b1));
}
// cp.async a 128-row x 64-half chunk into stage offset (4 iters of 256 threads)
__device__ __forceinline__ void cp_rows128(uint32_t sbase, const __half* base, int k0, int tid) {
    #pragma unroll
    for (int i = 0; i < 4; i++) {
        int tx = tid + i * 256;            // 0..1023
        int row = tx >> 3, seg = tx & 7;
        cp16(sbase + row * ROWB + seg * 16, base + (size_t)row * D + k0 + seg * 8);
    }
}

// ================= init / sort / prep / lnc / zbuild / gather =================
__global__ void k_init(const float* __restrict__ x) {
    int i = blockIdx.x * 256 + threadIdx.x;
    g_x[i] = x[i];
    g_agg[i] = 0u;
    if (i < N_NODES) g_cnt[i] = 0;
}

__global__ void k_hist(const int* __restrict__ dst) {
    int e = blockIdx.x * 256 + threadIdx.x;
    atomicAdd(&g_cnt[dst[e]], 1);
}

// exclusive scan over g_cnt[8192] -> g_cur (scatter cursors). 1 block, 1024 threads.
__global__ __launch_bounds__(1024) void k_scan() {
    __shared__ int wsum[32];
    int t = threadIdx.x;
    int base = t * 8;
    int v[8];
    int s = 0;
    #pragma unroll
    for (int i = 0; i < 8; i++) { v[i] = g_cnt[base + i]; s += v[i]; }
    int lane = t & 31, wid = t >> 5;
    int ps = s;
    #pragma unroll
    for (int o = 1; o < 32; o <<= 1) {
        int n = __shfl_up_sync(0xffffffffu, ps, o);
        if (lane >= o) ps += n;
    }
    if (lane == 31) wsum[wid] = ps;
    __syncthreads();
    if (wid == 0) {
        int ws = wsum[lane];
        #pragma unroll
        for (int o = 1; o < 32; o <<= 1) {
            int n = __shfl_up_sync(0xffffffffu, ws, o);
            if (lane >= o) ws += n;
        }
        wsum[lane] = ws;
    }
    __syncthreads();
    int run = ps - s + (wid > 0 ? wsum[wid - 1] : 0);
    #pragma unroll
    for (int i = 0; i < 8; i++) { g_cur[base + i] = run; run += v[i]; }
}

__global__ void k_scatter(const int* __restrict__ src, const int* __restrict__ dst) {
    int e = blockIdx.x * 256 + threadIdx.x;
    int d = dst[e];
    int p = atomicAdd(&g_cur[d], 1);
    g_eDst[p] = d;
    g_eSrc[p] = src[e];
}

// fp16 weight prep: mats 0..8: l=m/3; r0: Wd=W1top-W1bot; r1: Wb=W1bot; r2: W2^T
// mat 9: ffnW1^T ; 10: ffnW2^T.  Image [n][k] row-major fp16.
__global__ void k_prep16(const float* __restrict__ W1, const float* __restrict__ W2,
                         const float* __restrict__ fW1, const float* __restrict__ fW2,
                         __half* __restrict__ img) {
    int m = blockIdx.y;
    int e = blockIdx.x * 256 + threadIdx.x;
    int n = e & 511, k = e >> 9;
    float w;
    if (m < 9) {
        int l = m / 3, r = m % 3;
        const float* base = W1 + (size_t)l * 2 * D * D;
        if (r == 0)      w = base[(size_t)k * D + n] - base[(size_t)(D + k) * D + n];
        else if (r == 1) w = base[(size_t)(D + k) * D + n];
        else             w = W2[((size_t)l * D + k) * D + n];
    } else if (m == 9)   w = fW1[(size_t)k * D + n];
    else                 w = fW2[(size_t)k * D + n];
    img[(size_t)m * D * D + (size_t)n * D + k] = __float2half(w);
}

// fused combine (optional) + LayerNorm -> fp16.
__global__ __launch_bounds__(128) void k_lnc(int useAgg,
                                             const float* __restrict__ b2,
                                             const float* __restrict__ gamma,
                                             const float* __restrict__ beta,
                                             __half* __restrict__ out) {
    __shared__ float red[8];
    int row = blockIdx.x;
    int t = threadIdx.x;
    size_t base = (size_t)row * D + t * 4;
    float4 v = *(const float4*)(g_x + base);
    if (useAgg) {
        uint4 u = *(const uint4*)(g_agg + base);
        *(uint4*)(g_agg + base) = make_uint4(0u, 0u, 0u, 0u);
        float4 bv = ((const float4*)b2)[t];
        float m0 = u.x ? fdec(u.x) + bv.x : 0.f;
        float m1 = u.y ? fdec(u.y) + bv.y : 0.f;
        float m2 = u.z ? fdec(u.z) + bv.z : 0.f;
        float m3 = u.w ? fdec(u.w) + bv.w : 0.f;
        v.x += fmaxf(m0, 0.f); v.y += fmaxf(m1, 0.f);
        v.z += fmaxf(m2, 0.f); v.w += fmaxf(m3, 0.f);
        *(float4*)(g_x + base) = v;
    }
    float s = v.x + v.y + v.z + v.w;
    #pragma unroll
    for (int o = 16; o > 0; o >>= 1) s += __shfl_xor_sync(0xffffffffu, s, o);
    if ((t & 31) == 0) red[t >> 5] = s;
    __syncthreads();
    if (t == 0) red[4] = red[0] + red[1] + red[2] + red[3];
    __syncthreads();
    float mu = red[4] * (1.0f / D);
    __syncthreads();
    float dx = v.x - mu, dy = v.y - mu, dz = v.z - mu, dw = v.w - mu;
    float q = dx * dx + dy * dy + dz * dz + dw * dw;
    #pragma unroll
    for (int o = 16; o > 0; o >>= 1) q += __shfl_xor_sync(0xffffffffu, q, o);
    if ((t & 31) == 0) red[t >> 5] = q;
    __syncthreads();
    if (t == 0) red[4] = red[0] + red[1] + red[2] + red[3];
    __syncthreads();
    float rstd = rsqrtf(red[4] * (1.0f / D) + 1e-5f);
    float4 g4 = ((const float4*)gamma)[t];
    float4 b4 = ((const float4*)beta)[t];
    __half2 h0 = __floats2half2_rn(dx * rstd * g4.x + b4.x, dy * rstd * g4.y + b4.y);
    __half2 h1 = __floats2half2_rn(dz * rstd * g4.z + b4.z, dw * rstd * g4.w + b4.w);
    *(uint2*)(out + base) = make_uint2(*(uint32_t*)&h0, *(uint32_t*)&h1);
}

// Z build (sorted order, fp16): Z[p][k] = relu_h(A16[g_eDst[p]][k] + B16[g_eSrc[p]][k])
__global__ __launch_bounds__(256) void k_zbuild() {
    int e = blockIdx.x * 8 + (threadIdx.x >> 5);
    int sg = threadIdx.x & 31;
    int de = g_eDst[e], se = g_eSrc[e];
    const uint4* a = (const uint4*)(g_A16 + (size_t)de * D);
    const uint4* b = (const uint4*)(g_B16 + (size_t)se * D);
    uint4* z = (uint4*)(g_Z + (size_t)e * D);
    const __half2 zero2 = __floats2half2_rn(0.f, 0.f);
    #pragma unroll
    for (int i = 0; i < 2; i++) {
        int s = sg + i * 32;
        uint4 av = a[s], bv = b[s];
        uint4 r;
        __half2 h;
        h = __hmax2(__hadd2(*(__half2*)&av.x, *(__half2*)&bv.x), zero2); r.x = *(uint32_t*)&h;
        h = __hmax2(__hadd2(*(__half2*)&av.y, *(__half2*)&bv.y), zero2); r.y = *(uint32_t*)&h;
        h = __hmax2(__hadd2(*(__half2*)&av.z, *(__half2*)&bv.z), zero2); r.z = *(uint32_t*)&h;
        h = __hmax2(__hadd2(*(__half2*)&av.w, *(__half2*)&bv.w), zero2); r.w = *(uint32_t*)&h;
        z[s] = r;
    }
}

__global__ __launch_bounds__(128) void k_gather(const float* __restrict__ y,
                                                const int* __restrict__ sel,
                                                float* __restrict__ out) {
    int r = blockIdx.x;
    int b = r >> 7, s = r & (S_SEL - 1);
    int node = b * NPG + sel[b * S_SEL + s];
    ((float4*)(out + (size_t)r * D))[threadIdx.x] =
        ((const float4*)(y + (size_t)node * D))[threadIdx.x];
}

// ================= dense fp16 GEMM (generic, R7 shape) =================
// grid(x = D/128 = 4, y = M/128), 256 threads, 2 CTAs/SM
__global__ __launch_bounds__(256, 2) void k_mma_gemm(
    const __half* __restrict__ Ain,
    const __half* __restrict__ w,
    const float* __restrict__ bias,
    const float* __restrict__ res,
    float* __restrict__ out,
    __half* __restrict__ out16,
    int relu)
{
    extern __shared__ char smem[];
    int tid = threadIdx.x;
    int n0 = blockIdx.x * BN;
    int m0 = blockIdx.y * BM;
    int lane = tid & 31, wm = (tid >> 5) & 1, wn = tid >> 6;

    uint32_t s[NSTG];
    #pragma unroll
    for (int i = 0; i < NSTG; i++) s[i] = smem_u32(smem + i * STAGE);
    const __half* abase = Ain + (size_t)m0 * D;
    const __half* wbase = w + (size_t)n0 * D;
    uint32_t aoff = (uint32_t)(wm * 64 + (lane & 7) + ((lane >> 3) & 1) * 8) * ROWB
                  + ((lane >> 4) & 1) * 16;
    uint32_t boff = (uint32_t)(wn * 32 + (lane & 7) + ((lane >= 16) ? 8 : 0)) * ROWB
                  + ((lane >> 3) & 1) * 16;

    float acc[4][4][4] = {};

    cp_rows128(s[0] + SA, abase, 0, tid);
    cp_rows128(s[0] + SW, wbase, 0, tid);
    cp_commit();
    cp_rows128(s[1] + SA, abase, BK, tid);
    cp_rows128(s[1] + SW, wbase, BK, tid);
    cp_commit();
    cp_wait<1>();
    __syncthreads();

    for (int c = 0; c < NCH; c++) {
        uint32_t sc = s[c % NSTG];
        if (c + 2 < NCH) {
            uint32_t sn = s[(c + 2) % NSTG];
            cp_rows128(sn + SA, abase, (c + 2) * BK, tid);
            cp_rows128(sn + SW, wbase, (c + 2) * BK, tid);
            cp_commit();
        }
        #pragma unroll
        for (int kh = 0; kh < 4; kh++) {
            uint32_t bh[2][4];
            #pragma unroll
            for (int np = 0; np < 2; np++)
                ldm_x4(bh[np], sc + SW + boff + np * 16 * ROWB + kh * 32);
            #pragma unroll
            for (int mf = 0; mf < 4; mf++) {
                uint32_t ah[4];
                ldm_x4(ah, sc + SA + aoff + mf * 16 * ROWB + kh * 32);
                #pragma unroll
                for (int np = 0; np < 2; np++) {
                    #pragma unroll
                    for (int j = 0; j < 2; j++)
                        mma_h(acc[mf][np * 2 + j], ah, bh[np][2 * j], bh[np][2 * j + 1]);
                }
            }
        }
        if (c + 2 < NCH) cp_wait<1>();
        else if (c + 1 < NCH) cp_wait<0>();
        __syncthreads();
    }

    #pragma unroll
    for (int mf = 0; mf < 4; mf++) {
        int r0 = m0 + wm * 64 + mf * 16 + (lane >> 2);
        int colb = n0 + wn * 32 + 2 * (lane & 3);
        #pragma unroll
        for (int nf = 0; nf < 4; nf++) {
            int col = colb + nf * 8;
            float2 bv = bias ? *(const float2*)(bias + col) : make_float2(0.f, 0.f);
            float c0 = acc[mf][nf][0] + bv.x, c1 = acc[mf][nf][1] + bv.y;
            float c2 = acc[mf][nf][2] + bv.x, c3 = acc[mf][nf][3] + bv.y;
            if (relu) {
                c0 = fmaxf(c0, 0.f); c1 = fmaxf(c1, 0.f);
                c2 = fmaxf(c2, 0.f); c3 = fmaxf(c3, 0.f);
            }
            if (res) {
                float2 r1v = *(const float2*)(res + (size_t)r0 * D + col);
                float2 r2v = *(const float2*)(res + (size_t)(r0 + 8) * D + col);
                c0 += r1v.x; c1 += r1v.y; c2 += r2v.x; c3 += r2v.y;
            }
            if (out) {
                *(float2*)(out + (size_t)r0 * D + col) = make_float2(c0, c1);
                *(float2*)(out + (size_t)(r0 + 8) * D + col) = make_float2(c2, c3);
            }
            if (out16) {
                __half2 h0 = __floats2half2_rn(c0, c1);
                __half2 h1 = __floats2half2_rn(c2, c3);
                *(uint32_t*)(out16 + (size_t)r0 * D + col) = *(uint32_t*)&h0;
                *(uint32_t*)(out16 + (size_t)(r0 + 8) * D + col) = *(uint32_t*)&h1;
            }
        }
    }
}

// ================= merged A|B node GEMM =================
// w is the combined [1024 x 512] image (Wd rows 0..511, Wb rows 512..1023).
__global__ __launch_bounds__(256, 2) void k_mma_ab(
    const __half* __restrict__ Hm,
    const __half* __restrict__ w,
    const float* __restrict__ b1,
    __half* __restrict__ A16,
    __half* __restrict__ B16)
{
    extern __shared__ char smem[];
    int tid = threadIdx.x;
    int n0 = blockIdx.x * BN;          // 0..896
    int m0 = blockIdx.y * BM;
    int lane = tid & 31, wm = (tid >> 5) & 1, wn = tid >> 6;

    bool isA = (n0 < D);
    __half* dstbuf = isA ? A16 : B16;
    int cbase = isA ? 0 : D;
    const float* bias = isA ? b1 : nullptr;

    uint32_t s[NSTG];
    #pragma unroll
    for (int i = 0; i < NSTG; i++) s[i] = smem_u32(smem + i * STAGE);
    const __half* abase = Hm + (size_t)m0 * D;
    const __half* wbase = w + (size_t)n0 * D;
    uint32_t aoff = (uint32_t)(wm * 64 + (lane & 7) + ((lane >> 3) & 1) * 8) * ROWB
                  + ((lane >> 4) & 1) * 16;
    uint32_t boff = (uint32_t)(wn * 32 + (lane & 7) + ((lane >= 16) ? 8 : 0)) * ROWB
                  + ((lane >> 3) & 1) * 16;

    float acc[4][4][4] = {};

    cp_rows128(s[0] + SA, abase, 0, tid);
    cp_rows128(s[0] + SW, wbase, 0, tid);
    cp_commit();
    cp_rows128(s[1] + SA, abase, BK, tid);
    cp_rows128(s[1] + SW, wbase, BK, tid);
    cp_commit();
    cp_wait<1>();
    __syncthreads();

    for (int c = 0; c < NCH; c++) {
        uint32_t sc = s[c % NSTG];
        if (c + 2 < NCH) {
            uint32_t sn = s[(c + 2) % NSTG];
            cp_rows128(sn + SA, abase, (c + 2) * BK, tid);
            cp_rows128(sn + SW, wbase, (c + 2) * BK, tid);
            cp_commit();
        }
        #pragma unroll
        for (int kh = 0; kh < 4; kh++) {
            uint32_t bh[2][4];
            #pragma unroll
            for (int np = 0; np < 2; np++)
                ldm_x4(bh[np], sc + SW + boff + np * 16 * ROWB + kh * 32);
            #pragma unroll
            for (int mf = 0; mf < 4; mf++) {
                uint32_t ah[4];
                ldm_x4(ah, sc + SA + aoff + mf * 16 * ROWB + kh * 32);
                #pragma unroll
                for (int np = 0; np < 2; np++) {
                    #pragma unroll
                    for (int j = 0; j < 2; j++)
                        mma_h(acc[mf][np * 2 + j], ah, bh[np][2 * j], bh[np][2 * j + 1]);
                }
            }
        }
        if (c + 2 < NCH) cp_wait<1>();
        else if (c + 1 < NCH) cp_wait<0>();
        __syncthreads();
    }

    #pragma unroll
    for (int mf = 0; mf < 4; mf++) {
        int r0 = m0 + wm * 64 + mf * 16 + (lane >> 2);
        int colb = n0 + wn * 32 + 2 * (lane & 3);
        #pragma unroll
        for (int nf = 0; nf < 4; nf++) {
            int col = colb + nf * 8;
            float2 bv = bias ? *(const float2*)(bias + col) : make_float2(0.f, 0.f);
            float c0 = acc[mf][nf][0] + bv.x, c1 = acc[mf][nf][1] + bv.y;
            float c2 = acc[mf][nf][2] + bv.x, c3 = acc[mf][nf][3] + bv.y;
            int dc = col - cbase;
            __half2 h0 = __floats2half2_rn(c0, c1);
            __half2 h1 = __floats2half2_rn(c2, c3);
            *(uint32_t*)(dstbuf + (size_t)r0 * D + dc) = *(uint32_t*)&h0;
            *(uint32_t*)(dstbuf + (size_t)(r0 + 8) * D + dc) = *(uint32_t*)&h1;
        }
    }
}

// ================= edge GEMM: Zh(sorted) @ W2h -> smem segment-reduce -> atomicMax =================
// grid(x = D/128 = 4, y = E/128 = 1024), 256 threads, 2 CTAs/SM
__global__ __launch_bounds__(256, 2) void k_mma_edge(
    const __half* __restrict__ w16,
    const float* __restrict__ b2,
    unsigned* __restrict__ agg)
{
    extern __shared__ char smem[];
    int tid = threadIdx.x;
    int n0 = blockIdx.x * BN;
    int e0 = blockIdx.y * BM;
    int lane = tid & 31, wm = (tid >> 5) & 1, wn = tid >> 6;

    int* sDst = (int*)(smem + SM_IDX);
    if (tid < 128) sDst[tid] = g_eDst[e0 + tid];

    uint32_t s[NSTG];
    #pragma unroll
    for (int i = 0; i < NSTG; i++) s[i] = smem_u32(smem + i * STAGE);
    const __half* abase = g_Z + (size_t)e0 * D;
    const __half* wbase = w16 + (size_t)n0 * D;
    uint32_t aoff = (uint32_t)(wm * 64 + (lane & 7) + ((lane >> 3) & 1) * 8) * ROWB
                  + ((lane >> 4) & 1) * 16;
    uint32_t boff = (uint32_t)(wn * 32 + (lane & 7) + ((lane >= 16) ? 8 : 0)) * ROWB
                  + ((lane >> 3) & 1) * 16;

    float acc[4][4][4] = {};

    cp_rows128(s[0] + SA, abase, 0, tid);
    cp_rows128(s[0] + SW, wbase, 0, tid);
    cp_commit();
    cp_rows128(s[1] + SA, abase, BK, tid);
    cp_rows128(s[1] + SW, wbase, BK, tid);
    cp_commit();
    cp_wait<1>();
    __syncthreads();

    for (int c = 0; c < NCH; c++) {
        uint32_t sc = s[c % NSTG];
        if (c + 2 < NCH) {
            uint32_t sn = s[(c + 2) % NSTG];
            cp_rows128(sn + SA, abase, (c + 2) * BK, tid);
            cp_rows128(sn + SW, wbase, (c + 2) * BK, tid);
            cp_commit();
        }
        #pragma unroll
        for (int kh = 0; kh < 4; kh++) {
            uint32_t bh[2][4];
            #pragma unroll
            for (int np = 0; np < 2; np++)
                ldm_x4(bh[np], sc + SW + boff + np * 16 * ROWB + kh * 32);
            #pragma unroll
            for (int mf = 0; mf < 4; mf++) {
                uint32_t ah[4];
                ldm_x4(ah, sc + SA + aoff + mf * 16 * ROWB + kh * 32);
                #pragma unroll
                for (int np = 0; np < 2; np++) {
                    #pragma unroll
                    for (int j = 0; j < 2; j++)
                        mma_h(acc[mf][np * 2 + j], ah, bh[np][2 * j], bh[np][2 * j + 1]);
                }
            }
        }
        if (c + 2 < NCH) cp_wait<1>();
        else if (c + 1 < NCH) cp_wait<0>();
        __syncthreads();
    }

    // ---- epilogue: acc -> smem f32 tile (stages dead), segment-reduce by dst ----
    float* T = (float*)smem;   // [128][TPAD]
    #pragma unroll
    for (int mf = 0; mf < 4; mf++) {
        int r0 = wm * 64 + mf * 16 + (lane >> 2);
        int cl = wn * 32 + 2 * (lane & 3);
        #pragma unroll
        for (int nf = 0; nf < 4; nf++) {
            *(float2*)&T[r0 * TPAD + cl + nf * 8] =
                make_float2(acc[mf][nf][0], acc[mf][nf][1]);
            *(float2*)&T[(r0 + 8) * TPAD + cl + nf * 8] =
                make_float2(acc[mf][nf][2], acc[mf][nf][3]);
        }
    }
    __syncthreads();

    // 256 threads: col = tid&127, half = tid>>7 scans 64 sorted rows.
    {
        int col = tid & 127, half = tid >> 7;
        float thr = -b2[n0 + col];
        unsigned* aggcol = agg + n0 + col;
        int rbeg = half * 64, rend = rbeg + 64;
        int prevd = sDst[rbeg];
        float run = -FLT_MAX;
        for (int r = rbeg; r < rend; r++) {
            int d = sDst[r];
            float v = T[r * TPAD + col];
            if (d != prevd) {
                if (run > thr) atomicMax(aggcol + (size_t)prevd * D, fenc(run));
                prevd = d;
                run = v;
            } else {
                run = fmaxf(run, v);
            }
        }
        if (run > thr) atomicMax(aggcol + (size_t)prevd * D, fenc(run));
    }
}

// ================= host launcher =================
extern "C" void kernel_launch(void* const* d_in, const int* in_sizes, int n_in,
                              void* d_out, int out_size) {
    const float* x       = (const float*)d_in[0];
    const int*   eidx    = (const int*)d_in[1];
    const int*   sel     = (const int*)d_in[2];
    const float* conv_W1 = (const float*)d_in[4];
    const float* conv_b1 = (const float*)d_in[5];
    const float* conv_W2 = (const float*)d_in[6];
    const float* conv_b2 = (const float*)d_in[7];
    const float* ln1_g   = (const float*)d_in[8];
    const float* ln1_b   = (const float*)d_in[9];
    const float* ln2_g   = (const float*)d_in[10];
    const float* ln2_b   = (const float*)d_in[11];
    const float* ffn_W1  = (const float*)d_in[12];
    const float* ffn_b1  = (const float*)d_in[13];
    const float* ffn_W2  = (const float*)d_in[14];
    const float* ffn_b2  = (const float*)d_in[15];
    float* out = (float*)d_out;

    const int* src = eidx;
    const int* dst = eidx + E_EDGES;

    float *gx, *gout;
    unsigned* gagg;
    __half *gh16, *gt16, *ga16, *gb16, *gw16;
    cudaGetSymbolAddress((void**)&gx, g_x);
    cudaGetSymbolAddress((void**)&gout, g_out);
    cudaGetSymbolAddress((void**)&gagg, g_agg);
    cudaGetSymbolAddress((void**)&gh16, g_h16);
    cudaGetSymbolAddress((void**)&gt16, g_t16);
    cudaGetSymbolAddress((void**)&ga16, g_A16);
    cudaGetSymbolAddress((void**)&gb16, g_B16);
    cudaGetSymbolAddress((void**)&gw16, g_W16);

    cudaFuncSetAttribute(k_mma_gemm, cudaFuncAttributeMaxDynamicSharedMemorySize, SMEM_GEMM);
    cudaFuncSetAttribute(k_mma_ab,   cudaFuncAttributeMaxDynamicSharedMemorySize, SMEM_GEMM);
    cudaFuncSetAttribute(k_mma_edge, cudaFuncAttributeMaxDynamicSharedMemorySize, SMEM_EDGE);

    auto W = [&](int m) { return gw16 + (size_t)m * D * D; };

    const int ND = N_NODES * D;

    k_init<<<ND / 256, 256>>>(x);
    k_hist<<<E_EDGES / 256, 256>>>(dst);
    {
        dim3 grid(1024, NMAT);
        k_prep16<<<grid, 256>>>(conv_W1, conv_W2, ffn_W1, ffn_W2, gw16);
    }
    k_scan<<<1, 1024>>>();
    k_scatter<<<E_EDGES / 256, 256>>>(src, dst);

    dim3 ggemm(D / BN, N_NODES / BM);        // (4, 64)
    dim3 gab(2 * D / BN, N_NODES / BM);      // (8, 64) merged A|B
    dim3 gedge(D / BN, E_EDGES / BM);        // (4, 1024)

    for (int l = 0; l < L_LAYERS; l++) {
        if (l == 0)
            k_lnc<<<N_NODES, 128>>>(0, conv_b2, ln1_g, ln1_b, gh16);
        else
            k_lnc<<<N_NODES, 128>>>(1, conv_b2 + (size_t)(l - 1) * D, ln1_g, ln1_b, gh16);
        k_mma_ab<<<gab, 256, SMEM_GEMM>>>(gh16, W(l * 3 + 0),
                                          conv_b1 + (size_t)l * D, ga16, gb16);
        k_zbuild<<<E_EDGES / 8, 256>>>();
        k_mma_edge<<<gedge, 256, SMEM_EDGE>>>(W(l * 3 + 2),
                                              conv_b2 + (size_t)l * D, gagg);
    }

    k_lnc<<<N_NODES, 128>>>(1, conv_b2 + (size_t)2 * D, ln2_g, ln2_b, gh16);
    k_mma_gemm<<<ggemm, 256, SMEM_GEMM>>>(gh16, W(9), ffn_b1, nullptr,
                                          nullptr, gt16, 1);
    k_mma_gemm<<<ggemm, 256, SMEM_GEMM>>>(gt16, W(10), ffn_b2, gx,
                                          gout, nullptr, 0);
    k_gather<<<B_GR * S_SEL, 128>>>(gout, sel, out);
}

// round 14
// speedup vs baseline: 1.6472x; 1.2427x over previous
#include <cuda_runtime.h>
#include <cuda_fp16.h>
#include <cstdint>
#include <cfloat>

// Problem constants (fixed shapes)
constexpr int N_NODES = 8192;
constexpr int D = 512;
constexpr int E_EDGES = 131072;
constexpr int B_GR = 16;
constexpr int NPG = 512;
constexpr int S_SEL = 128;
constexpr int L_LAYERS = 3;
constexpr int NSEL = B_GR * S_SEL;   // 2048 selected rows

// GEMM tiling (proven shape)
constexpr int BM = 128;
constexpr int BN = 128;
constexpr int BK = 64;
constexpr int NCH = D / BK;
constexpr int NMAT = 11;

constexpr int ROWB = 144;
constexpr int SA = 0;
constexpr int SW = 18432;
constexpr int STAGE = 36864;
constexpr int NSTG = 3;
constexpr int SM_IDX = NSTG * STAGE;
constexpr int SMEM_GEMM = NSTG * STAGE;
constexpr int SMEM_EDGE = NSTG * STAGE + 512;
constexpr int TPAD = 132;

// -------- static device scratch --------
__device__ float    g_x[N_NODES * D];
__device__ unsigned g_agg[N_NODES * D];
__device__ __align__(16) __half g_h16[N_NODES * D];
__device__ __align__(16) __half g_t16[N_NODES * D];
__device__ __align__(16) __half g_A16[N_NODES * D];
__device__ __align__(16) __half g_B16[N_NODES * D];
__device__ __align__(16) __half g_Z[(size_t)E_EDGES * D];
__device__ __align__(16) __half g_W16[(size_t)NMAT * D * D];
__device__ float    g_res[NSEL * D];        // compact residual for FFN
// edge sort / filter scratch
__device__ int g_cnt[N_NODES], g_cur[N_NODES];
__device__ int g_cnt3[N_NODES], g_cur3[N_NODES];
__device__ int g_selmask[N_NODES];
__device__ int g_eDst[E_EDGES], g_eSrc[E_EDGES];
__device__ int g_eDst3[E_EDGES], g_eSrc3[E_EDGES];
__device__ int g_tot3;     // filtered edge count
__device__ int g_padE3;    // padded edge count
__device__ int g_tiles3;   // padded tile count

// ---------------- helpers ----------------
__device__ __forceinline__ unsigned fenc(float f) {
    unsigned b = __float_as_uint(f);
    return (b & 0x80000000u) ? ~b : (b | 0x80000000u);
}
__device__ __forceinline__ float fdec(unsigned u) {
    unsigned b = (u & 0x80000000u) ? (u & 0x7fffffffu) : ~u;
    return __uint_as_float(b);
}
__device__ __forceinline__ uint32_t smem_u32(const void* p) {
    uint32_t a;
    asm("{ .reg .u64 t; cvta.to.shared.u64 t, %1; cvt.u32.u64 %0, t; }" : "=r"(a) : "l"(p));
    return a;
}
__device__ __forceinline__ void cp16(uint32_t dst, const void* src) {
    asm volatile("cp.async.cg.shared.global [%0], [%1], 16;" :: "r"(dst), "l"(src) : "memory");
}
__device__ __forceinline__ void cp_commit() {
    asm volatile("cp.async.commit_group;" ::: "memory");
}
template <int N>
__device__ __forceinline__ void cp_wait() {
    asm volatile("cp.async.wait_group %0;" :: "n"(N) : "memory");
}
__device__ __forceinline__ void ldm_x4(uint32_t* r, uint32_t addr) {
    asm volatile("ldmatrix.sync.aligned.m8n8.x4.shared.b16 {%0,%1,%2,%3}, [%4];"
                 : "=r"(r[0]), "=r"(r[1]), "=r"(r[2]), "=r"(r[3]) : "r"(addr));
}
__device__ __forceinline__ void mma_h(float* d, const uint32_t* a, uint32_t b0, uint32_t b1) {
    asm volatile(
        "mma.sync.aligned.m16n8k16.row.col.f32.f16.f16.f32 "
        "{%0,%1,%2,%3}, {%4,%5,%6,%7}, {%8,%9}, {%0,%1,%2,%3};"
        : "+f"(d[0]), "+f"(d[1]), "+f"(d[2]), "+f"(d[3])
        : "r"(a[0]), "r"(a[1]), "r"(a[2]), "r"(a[3]), "r"(b0), "r"(b1));
}
__device__ __forceinline__ void cp_rows128(uint32_t sbase, const __half* base, int k0, int tid) {
    #pragma unroll
    for (int i = 0; i < 4; i++) {
        int tx = tid + i * 256;
        int row = tx >> 3, seg = tx & 7;
        cp16(sbase + row * ROWB + seg * 16, base + (size_t)row * D + k0 + seg * 8);
    }
}

// ================= prep kernels =================
__global__ void k_init(const float* __restrict__ x) {
    int i = blockIdx.x * 256 + threadIdx.x;
    g_x[i] = x[i];
    g_agg[i] = 0u;
    if (i < N_NODES) { g_cnt[i] = 0; g_cnt3[i] = 0; g_selmask[i] = 0; }
}

__global__ void k_mask(const int* __restrict__ sel) {
    int i = blockIdx.x * 256 + threadIdx.x;   // 0..2047
    int node = (i >> 7) * NPG + sel[i];
    g_selmask[node] = 1;
}

__global__ void k_hist(const int* __restrict__ dst) {
    int e = blockIdx.x * 256 + threadIdx.x;
    int d = dst[e];
    atomicAdd(&g_cnt[d], 1);
    if (g_selmask[d]) atomicAdd(&g_cnt3[d], 1);
}

// exclusive scan over cnt[8192] -> cur; optional grand total. 1 block, 1024 threads.
__global__ __launch_bounds__(1024) void k_scan(const int* __restrict__ cnt,
                                               int* __restrict__ cur,
                                               int* __restrict__ tot) {
    __shared__ int wsum[32];
    int t = threadIdx.x;
    int base = t * 8;
    int v[8];
    int s = 0;
    #pragma unroll
    for (int i = 0; i < 8; i++) { v[i] = cnt[base + i]; s += v[i]; }
    int lane = t & 31, wid = t >> 5;
    int ps = s;
    #pragma unroll
    for (int o = 1; o < 32; o <<= 1) {
        int n = __shfl_up_sync(0xffffffffu, ps, o);
        if (lane >= o) ps += n;
    }
    if (lane == 31) wsum[wid] = ps;
    __syncthreads();
    if (wid == 0) {
        int ws = wsum[lane];
        #pragma unroll
        for (int o = 1; o < 32; o <<= 1) {
            int n = __shfl_up_sync(0xffffffffu, ws, o);
            if (lane >= o) ws += n;
        }
        wsum[lane] = ws;
    }
    __syncthreads();
    int run = ps - s + (wid > 0 ? wsum[wid - 1] : 0);
    #pragma unroll
    for (int i = 0; i < 8; i++) { cur[base + i] = run; run += v[i]; }
    if (tot && t == 1023) *tot = run;
}

__global__ void k_scatter(const int* __restrict__ src, const int* __restrict__ dst) {
    int e = blockIdx.x * 256 + threadIdx.x;
    int d = dst[e], sr = src[e];
    int p = atomicAdd(&g_cur[d], 1);
    g_eDst[p] = d;
    g_eSrc[p] = sr;
    if (g_selmask[d]) {
        int p3 = atomicAdd(&g_cur3[d], 1);
        g_eDst3[p3] = d;
        g_eSrc3[p3] = sr;
    }
}

// pad filtered list to multiple of 128 by duplicating last edge (max-idempotent)
__global__ __launch_bounds__(256) void k_pad() {
    int tot = g_tot3;
    int pad = (tot + 127) & ~127;
    if (pad > E_EDGES) pad = E_EDGES;
    if (tot > 0) {
        int ld = g_eDst3[tot - 1], ls = g_eSrc3[tot - 1];
        for (int i = tot + threadIdx.x; i < pad; i += 256) {
            g_eDst3[i] = ld;
            g_eSrc3[i] = ls;
        }
    }
    if (threadIdx.x == 0) { g_padE3 = pad; g_tiles3 = pad / BM; }
}

// fp16 weight prep (as before)
__global__ void k_prep16(const float* __restrict__ W1, const float* __restrict__ W2,
                         const float* __restrict__ fW1, const float* __restrict__ fW2,
                         __half* __restrict__ img) {
    int m = blockIdx.y;
    int e = blockIdx.x * 256 + threadIdx.x;
    int n = e & 511, k = e >> 9;
    float w;
    if (m < 9) {
        int l = m / 3, r = m % 3;
        const float* base = W1 + (size_t)l * 2 * D * D;
        if (r == 0)      w = base[(size_t)k * D + n] - base[(size_t)(D + k) * D + n];
        else if (r == 1) w = base[(size_t)(D + k) * D + n];
        else             w = W2[((size_t)l * D + k) * D + n];
    } else if (m == 9)   w = fW1[(size_t)k * D + n];
    else                 w = fW2[(size_t)k * D + n];
    img[(size_t)m * D * D + (size_t)n * D + k] = __float2half(w);
}

// fused combine (optional) + LayerNorm -> fp16 (all nodes)
__global__ __launch_bounds__(128) void k_lnc(int useAgg,
                                             const float* __restrict__ b2,
                                             const float* __restrict__ gamma,
                                             const float* __restrict__ beta,
                                             __half* __restrict__ out) {
    __shared__ float red[8];
    int row = blockIdx.x;
    int t = threadIdx.x;
    size_t base = (size_t)row * D + t * 4;
    float4 v = *(const float4*)(g_x + base);
    if (useAgg) {
        uint4 u = *(const uint4*)(g_agg + base);
        *(uint4*)(g_agg + base) = make_uint4(0u, 0u, 0u, 0u);
        float4 bv = ((const float4*)b2)[t];
        float m0 = u.x ? fdec(u.x) + bv.x : 0.f;
        float m1 = u.y ? fdec(u.y) + bv.y : 0.f;
        float m2 = u.z ? fdec(u.z) + bv.z : 0.f;
        float m3 = u.w ? fdec(u.w) + bv.w : 0.f;
        v.x += fmaxf(m0, 0.f); v.y += fmaxf(m1, 0.f);
        v.z += fmaxf(m2, 0.f); v.w += fmaxf(m3, 0.f);
        *(float4*)(g_x + base) = v;
    }
    float s = v.x + v.y + v.z + v.w;
    #pragma unroll
    for (int o = 16; o > 0; o >>= 1) s += __shfl_xor_sync(0xffffffffu, s, o);
    if ((t & 31) == 0) red[t >> 5] = s;
    __syncthreads();
    if (t == 0) red[4] = red[0] + red[1] + red[2] + red[3];
    __syncthreads();
    float mu = red[4] * (1.0f / D);
    __syncthreads();
    float dx = v.x - mu, dy = v.y - mu, dz = v.z - mu, dw = v.w - mu;
    float q = dx * dx + dy * dy + dz * dz + dw * dw;
    #pragma unroll
    for (int o = 16; o > 0; o >>= 1) q += __shfl_xor_sync(0xffffffffu, q, o);
    if ((t & 31) == 0) red[t >> 5] = q;
    __syncthreads();
    if (t == 0) red[4] = red[0] + red[1] + red[2] + red[3];
    __syncthreads();
    float rstd = rsqrtf(red[4] * (1.0f / D) + 1e-5f);
    float4 g4 = ((const float4*)gamma)[t];
    float4 b4 = ((const float4*)beta)[t];
    __half2 h0 = __floats2half2_rn(dx * rstd * g4.x + b4.x, dy * rstd * g4.y + b4.y);
    __half2 h1 = __floats2half2_rn(dz * rstd * g4.z + b4.z, dw * rstd * g4.w + b4.w);
    *(uint2*)(out + base) = make_uint2(*(uint32_t*)&h0, *(uint32_t*)&h1);
}

// selected-rows combine + LN2 -> compact fp16 + compact fp32 residual.
// agg is read-only here (duplicate sel entries safe; k_init re-zeros agg each launch).
__global__ __launch_bounds__(128) void k_lnc_sel(const int* __restrict__ sel,
                                                 const float* __restrict__ b2,
                                                 const float* __restrict__ gamma,
                                                 const float* __restrict__ beta,
                                                 __half* __restrict__ hout) {
    __shared__ float red[8];
    int r = blockIdx.x;                 // 0..2047
    int t = threadIdx.x;
    int node = (r >> 7) * NPG + sel[r];
    size_t base = (size_t)node * D + t * 4;
    float4 v = *(const float4*)(g_x + base);
    uint4 u = *(const uint4*)(g_agg + base);
    float4 bv = ((const float4*)b2)[t];
    float m0 = u.x ? fdec(u.x) + bv.x : 0.f;
    float m1 = u.y ? fdec(u.y) + bv.y : 0.f;
    float m2 = u.z ? fdec(u.z) + bv.z : 0.f;
    float m3 = u.w ? fdec(u.w) + bv.w : 0.f;
    v.x += fmaxf(m0, 0.f); v.y += fmaxf(m1, 0.f);
    v.z += fmaxf(m2, 0.f); v.w += fmaxf(m3, 0.f);
    *(float4*)(g_res + (size_t)r * D + t * 4) = v;

    float s = v.x + v.y + v.z + v.w;
    #pragma unroll
    for (int o = 16; o > 0; o >>= 1) s += __shfl_xor_sync(0xffffffffu, s, o);
    if ((t & 31) == 0) red[t >> 5] = s;
    __syncthreads();
    if (t == 0) red[4] = red[0] + red[1] + red[2] + red[3];
    __syncthreads();
    float mu = red[4] * (1.0f / D);
    __syncthreads();
    float dx = v.x - mu, dy = v.y - mu, dz = v.z - mu, dw = v.w - mu;
    float q = dx * dx + dy * dy + dz * dz + dw * dw;
    #pragma unroll
    for (int o = 16; o > 0; o >>= 1) q += __shfl_xor_sync(0xffffffffu, q, o);
    if ((t & 31) == 0) red[t >> 5] = q;
    __syncthreads();
    if (t == 0) red[4] = red[0] + red[1] + red[2] + red[3];
    __syncthreads();
    float rstd = rsqrtf(red[4] * (1.0f / D) + 1e-5f);
    float4 g4 = ((const float4*)gamma)[t];
    float4 b4 = ((const float4*)beta)[t];
    __half2 h0 = __floats2half2_rn(dx * rstd * g4.x + b4.x, dy * rstd * g4.y + b4.y);
    __half2 h1 = __floats2half2_rn(dz * rstd * g4.z + b4.z, dw * rstd * g4.w + b4.w);
    *(uint2*)(hout + (size_t)r * D + t * 4) = make_uint2(*(uint32_t*)&h0, *(uint32_t*)&h1);
}

// Z build over an edge list (sorted, possibly filtered+padded)
__global__ __launch_bounds__(256) void k_zbuild(const int* __restrict__ eD,
                                                const int* __restrict__ eS,
                                                const int* __restrict__ dynCount) {
    int e = blockIdx.x * 8 + (threadIdx.x >> 5);
    if (dynCount && e >= *dynCount) return;
    int sg = threadIdx.x & 31;
    int de = eD[e], se = eS[e];
    const uint4* a = (const uint4*)(g_A16 + (size_t)de * D);
    const uint4* b = (const uint4*)(g_B16 + (size_t)se * D);
    uint4* z = (uint4*)(g_Z + (size_t)e * D);
    const __half2 zero2 = __floats2half2_rn(0.f, 0.f);
    #pragma unroll
    for (int i = 0; i < 2; i++) {
        int s = sg + i * 32;
        uint4 av = a[s], bv = b[s];
        uint4 r;
        __half2 h;
        h = __hmax2(__hadd2(*(__half2*)&av.x, *(__half2*)&bv.x), zero2); r.x = *(uint32_t*)&h;
        h = __hmax2(__hadd2(*(__half2*)&av.y, *(__half2*)&bv.y), zero2); r.y = *(uint32_t*)&h;
        h = __hmax2(__hadd2(*(__half2*)&av.z, *(__half2*)&bv.z), zero2); r.z = *(uint32_t*)&h;
        h = __hmax2(__hadd2(*(__half2*)&av.w, *(__half2*)&bv.w), zero2); r.w = *(uint32_t*)&h;
        z[s] = r;
    }
}

// ================= dense fp16 GEMM (generic) =================
__global__ __launch_bounds__(256, 2) void k_mma_gemm(
    const __half* __restrict__ Ain,
    const __half* __restrict__ w,
    const float* __restrict__ bias,
    const float* __restrict__ res,
    float* __restrict__ out,
    __half* __restrict__ out16,
    int relu)
{
    extern __shared__ char smem[];
    int tid = threadIdx.x;
    int n0 = blockIdx.x * BN;
    int m0 = blockIdx.y * BM;
    int lane = tid & 31, wm = (tid >> 5) & 1, wn = tid >> 6;

    uint32_t s[NSTG];
    #pragma unroll
    for (int i = 0; i < NSTG; i++) s[i] = smem_u32(smem + i * STAGE);
    const __half* abase = Ain + (size_t)m0 * D;
    const __half* wbase = w + (size_t)n0 * D;
    uint32_t aoff = (uint32_t)(wm * 64 + (lane & 7) + ((lane >> 3) & 1) * 8) * ROWB
                  + ((lane >> 4) & 1) * 16;
    uint32_t boff = (uint32_t)(wn * 32 + (lane & 7) + ((lane >= 16) ? 8 : 0)) * ROWB
                  + ((lane >> 3) & 1) * 16;

    float acc[4][4][4] = {};

    cp_rows128(s[0] + SA, abase, 0, tid);
    cp_rows128(s[0] + SW, wbase, 0, tid);
    cp_commit();
    cp_rows128(s[1] + SA, abase, BK, tid);
    cp_rows128(s[1] + SW, wbase, BK, tid);
    cp_commit();
    cp_wait<1>();
    __syncthreads();

    for (int c = 0; c < NCH; c++) {
        uint32_t sc = s[c % NSTG];
        if (c + 2 < NCH) {
            uint32_t sn = s[(c + 2) % NSTG];
            cp_rows128(sn + SA, abase, (c + 2) * BK, tid);
            cp_rows128(sn + SW, wbase, (c + 2) * BK, tid);
            cp_commit();
        }
        #pragma unroll
        for (int kh = 0; kh < 4; kh++) {
            uint32_t bh[2][4];
            #pragma unroll
            for (int np = 0; np < 2; np++)
                ldm_x4(bh[np], sc + SW + boff + np * 16 * ROWB + kh * 32);
            #pragma unroll
            for (int mf = 0; mf < 4; mf++) {
                uint32_t ah[4];
                ldm_x4(ah, sc + SA + aoff + mf * 16 * ROWB + kh * 32);
                #pragma unroll
                for (int np = 0; np < 2; np++) {
                    #pragma unroll
                    for (int j = 0; j < 2; j++)
                        mma_h(acc[mf][np * 2 + j], ah, bh[np][2 * j], bh[np][2 * j + 1]);
                }
            }
        }
        if (c + 2 < NCH) cp_wait<1>();
        else if (c + 1 < NCH) cp_wait<0>();
        __syncthreads();
    }

    #pragma unroll
    for (int mf = 0; mf < 4; mf++) {
        int r0 = m0 + wm * 64 + mf * 16 + (lane >> 2);
        int colb = n0 + wn * 32 + 2 * (lane & 3);
        #pragma unroll
        for (int nf = 0; nf < 4; nf++) {
            int col = colb + nf * 8;
            float2 bv = bias ? *(const float2*)(bias + col) : make_float2(0.f, 0.f);
            float c0 = acc[mf][nf][0] + bv.x, c1 = acc[mf][nf][1] + bv.y;
            float c2 = acc[mf][nf][2] + bv.x, c3 = acc[mf][nf][3] + bv.y;
            if (relu) {
                c0 = fmaxf(c0, 0.f); c1 = fmaxf(c1, 0.f);
                c2 = fmaxf(c2, 0.f); c3 = fmaxf(c3, 0.f);
            }
            if (res) {
                float2 r1v = *(const float2*)(res + (size_t)r0 * D + col);
                float2 r2v = *(const float2*)(res + (size_t)(r0 + 8) * D + col);
                c0 += r1v.x; c1 += r1v.y; c2 += r2v.x; c3 += r2v.y;
            }
            if (out) {
                *(float2*)(out + (size_t)r0 * D + col) = make_float2(c0, c1);
                *(float2*)(out + (size_t)(r0 + 8) * D + col) = make_float2(c2, c3);
            }
            if (out16) {
                __half2 h0 = __floats2half2_rn(c0, c1);
                __half2 h1 = __floats2half2_rn(c2, c3);
                *(uint32_t*)(out16 + (size_t)r0 * D + col) = *(uint32_t*)&h0;
                *(uint32_t*)(out16 + (size_t)(r0 + 8) * D + col) = *(uint32_t*)&h1;
            }
        }
    }
}

// ================= merged A|B node GEMM =================
__global__ __launch_bounds__(256, 2) void k_mma_ab(
    const __half* __restrict__ Hm,
    const __half* __restrict__ w,
    const float* __restrict__ b1,
    __half* __restrict__ A16,
    __half* __restrict__ B16)
{
    extern __shared__ char smem[];
    int tid = threadIdx.x;
    int n0 = blockIdx.x * BN;
    int m0 = blockIdx.y * BM;
    int lane = tid & 31, wm = (tid >> 5) & 1, wn = tid >> 6;

    bool isA = (n0 < D);
    __half* dstbuf = isA ? A16 : B16;
    int cbase = isA ? 0 : D;
    const float* bias = isA ? b1 : nullptr;

    uint32_t s[NSTG];
    #pragma unroll
    for (int i = 0; i < NSTG; i++) s[i] = smem_u32(smem + i * STAGE);
    const __half* abase = Hm + (size_t)m0 * D;
    const __half* wbase = w + (size_t)n0 * D;
    uint32_t aoff = (uint32_t)(wm * 64 + (lane & 7) + ((lane >> 3) & 1) * 8) * ROWB
                  + ((lane >> 4) & 1) * 16;
    uint32_t boff = (uint32_t)(wn * 32 + (lane & 7) + ((lane >= 16) ? 8 : 0)) * ROWB
                  + ((lane >> 3) & 1) * 16;

    float acc[4][4][4] = {};

    cp_rows128(s[0] + SA, abase, 0, tid);
    cp_rows128(s[0] + SW, wbase, 0, tid);
    cp_commit();
    cp_rows128(s[1] + SA, abase, BK, tid);
    cp_rows128(s[1] + SW, wbase, BK, tid);
    cp_commit();
    cp_wait<1>();
    __syncthreads();

    for (int c = 0; c < NCH; c++) {
        uint32_t sc = s[c % NSTG];
        if (c + 2 < NCH) {
            uint32_t sn = s[(c + 2) % NSTG];
            cp_rows128(sn + SA, abase, (c + 2) * BK, tid);
            cp_rows128(sn + SW, wbase, (c + 2) * BK, tid);
            cp_commit();
        }
        #pragma unroll
        for (int kh = 0; kh < 4; kh++) {
            uint32_t bh[2][4];
            #pragma unroll
            for (int np = 0; np < 2; np++)
                ldm_x4(bh[np], sc + SW + boff + np * 16 * ROWB + kh * 32);
            #pragma unroll
            for (int mf = 0; mf < 4; mf++) {
                uint32_t ah[4];
                ldm_x4(ah, sc + SA + aoff + mf * 16 * ROWB + kh * 32);
                #pragma unroll
                for (int np = 0; np < 2; np++) {
                    #pragma unroll
                    for (int j = 0; j < 2; j++)
                        mma_h(acc[mf][np * 2 + j], ah, bh[np][2 * j], bh[np][2 * j + 1]);
                }
            }
        }
        if (c + 2 < NCH) cp_wait<1>();
        else if (c + 1 < NCH) cp_wait<0>();
        __syncthreads();
    }

    #pragma unroll
    for (int mf = 0; mf < 4; mf++) {
        int r0 = m0 + wm * 64 + mf * 16 + (lane >> 2);
        int colb = n0 + wn * 32 + 2 * (lane & 3);
        #pragma unroll
        for (int nf = 0; nf < 4; nf++) {
            int col = colb + nf * 8;
            float2 bv = bias ? *(const float2*)(bias + col) : make_float2(0.f, 0.f);
            float c0 = acc[mf][nf][0] + bv.x, c1 = acc[mf][nf][1] + bv.y;
            float c2 = acc[mf][nf][2] + bv.x, c3 = acc[mf][nf][3] + bv.y;
            int dc = col - cbase;
            __half2 h0 = __floats2half2_rn(c0, c1);
            __half2 h1 = __floats2half2_rn(c2, c3);
            *(uint32_t*)(dstbuf + (size_t)r0 * D + dc) = *(uint32_t*)&h0;
            *(uint32_t*)(dstbuf + (size_t)(r0 + 8) * D + dc) = *(uint32_t*)&h1;
        }
    }
}

// ================= edge GEMM: Z(sorted list) @ W2 -> smem segment-reduce -> atomicMax =================
__global__ __launch_bounds__(256, 2) void k_mma_edge(
    const __half* __restrict__ w16,
    const float* __restrict__ b2,
    unsigned* __restrict__ agg,
    const int* __restrict__ eD,
    const int* __restrict__ tileLimit)
{
    extern __shared__ char smem[];
    int e0 = blockIdx.y * BM;
    if (tileLimit && blockIdx.y >= *tileLimit) return;
    int tid = threadIdx.x;
    int n0 = blockIdx.x * BN;
    int lane = tid & 31, wm = (tid >> 5) & 1, wn = tid >> 6;

    int* sDst = (int*)(smem + SM_IDX);
    if (tid < 128) sDst[tid] = eD[e0 + tid];

    uint32_t s[NSTG];
    #pragma unroll
    for (int i = 0; i < NSTG; i++) s[i] = smem_u32(smem + i * STAGE);
    const __half* abase = g_Z + (size_t)e0 * D;
    const __half* wbase = w16 + (size_t)n0 * D;
    uint32_t aoff = (uint32_t)(wm * 64 + (lane & 7) + ((lane >> 3) & 1) * 8) * ROWB
                  + ((lane >> 4) & 1) * 16;
    uint32_t boff = (uint32_t)(wn * 32 + (lane & 7) + ((lane >= 16) ? 8 : 0)) * ROWB
                  + ((lane >> 3) & 1) * 16;

    float acc[4][4][4] = {};

    cp_rows128(s[0] + SA, abase, 0, tid);
    cp_rows128(s[0] + SW, wbase, 0, tid);
    cp_commit();
    cp_rows128(s[1] + SA, abase, BK, tid);
    cp_rows128(s[1] + SW, wbase, BK, tid);
    cp_commit();
    cp_wait<1>();
    __syncthreads();

    for (int c = 0; c < NCH; c++) {
        uint32_t sc = s[c % NSTG];
        if (c + 2 < NCH) {
            uint32_t sn = s[(c + 2) % NSTG];
            cp_rows128(sn + SA, abase, (c + 2) * BK, tid);
            cp_rows128(sn + SW, wbase, (c + 2) * BK, tid);
            cp_commit();
        }
        #pragma unroll
        for (int kh = 0; kh < 4; kh++) {
            uint32_t bh[2][4];
            #pragma unroll
            for (int np = 0; np < 2; np++)
                ldm_x4(bh[np], sc + SW + boff + np * 16 * ROWB + kh * 32);
            #pragma unroll
            for (int mf = 0; mf < 4; mf++) {
                uint32_t ah[4];
                ldm_x4(ah, sc + SA + aoff + mf * 16 * ROWB + kh * 32);
                #pragma unroll
                for (int np = 0; np < 2; np++) {
                    #pragma unroll
                    for (int j = 0; j < 2; j++)
                        mma_h(acc[mf][np * 2 + j], ah, bh[np][2 * j], bh[np][2 * j + 1]);
                }
            }
        }
        if (c + 2 < NCH) cp_wait<1>();
        else if (c + 1 < NCH) cp_wait<0>();
        __syncthreads();
    }

    // epilogue: acc -> smem f32 tile, segment-reduce by sorted dst, gated atomics
    float* T = (float*)smem;
    #pragma unroll
    for (int mf = 0; mf < 4; mf++) {
        int r0 = wm * 64 + mf * 16 + (lane >> 2);
        int cl = wn * 32 + 2 * (lane & 3);
        #pragma unroll
        for (int nf = 0; nf < 4; nf++) {
            *(float2*)&T[r0 * TPAD + cl + nf * 8] =
                make_float2(acc[mf][nf][0], acc[mf][nf][1]);
            *(float2*)&T[(r0 + 8) * TPAD + cl + nf * 8] =
                make_float2(acc[mf][nf][2], acc[mf][nf][3]);
        }
    }
    __syncthreads();

    {
        int col = tid & 127, half = tid >> 7;
        float thr = -b2[n0 + col];
        unsigned* aggcol = agg + n0 + col;
        int rbeg = half * 64, rend = rbeg + 64;
        int prevd = sDst[rbeg];
        float run = -FLT_MAX;
        for (int r = rbeg; r < rend; r++) {
            int d = sDst[r];
            float v = T[r * TPAD + col];
            if (d != prevd) {
                if (run > thr) atomicMax(aggcol + (size_t)prevd * D, fenc(run));
                prevd = d;
                run = v;
            } else {
                run = fmaxf(run, v);
            }
        }
        if (run > thr) atomicMax(aggcol + (size_t)prevd * D, fenc(run));
    }
}

// ================= host launcher =================
extern "C" void kernel_launch(void* const* d_in, const int* in_sizes, int n_in,
                              void* d_out, int out_size) {
    const float* x       = (const float*)d_in[0];
    const int*   eidx    = (const int*)d_in[1];
    const int*   sel     = (const int*)d_in[2];
    const float* conv_W1 = (const float*)d_in[4];
    const float* conv_b1 = (const float*)d_in[5];
    const float* conv_W2 = (const float*)d_in[6];
    const float* conv_b2 = (const float*)d_in[7];
    const float* ln1_g   = (const float*)d_in[8];
    const float* ln1_b   = (const float*)d_in[9];
    const float* ln2_g   = (const float*)d_in[10];
    const float* ln2_b   = (const float*)d_in[11];
    const float* ffn_W1  = (const float*)d_in[12];
    const float* ffn_b1  = (const float*)d_in[13];
    const float* ffn_W2  = (const float*)d_in[14];
    const float* ffn_b2  = (const float*)d_in[15];
    float* out = (float*)d_out;

    const int* src = eidx;
    const int* dst = eidx + E_EDGES;

    float *gres;
    unsigned* gagg;
    __half *gh16, *gt16, *ga16, *gb16, *gw16;
    int *gcnt, *gcur, *gcnt3, *gcur3, *geD, *geD3, *gtot3, *gpadE3, *gtiles3;
    cudaGetSymbolAddress((void**)&gres, g_res);
    cudaGetSymbolAddress((void**)&gagg, g_agg);
    cudaGetSymbolAddress((void**)&gh16, g_h16);
    cudaGetSymbolAddress((void**)&gt16, g_t16);
    cudaGetSymbolAddress((void**)&ga16, g_A16);
    cudaGetSymbolAddress((void**)&gb16, g_B16);
    cudaGetSymbolAddress((void**)&gw16, g_W16);
    cudaGetSymbolAddress((void**)&gcnt, g_cnt);
    cudaGetSymbolAddress((void**)&gcur, g_cur);
    cudaGetSymbolAddress((void**)&gcnt3, g_cnt3);
    cudaGetSymbolAddress((void**)&gcur3, g_cur3);
    cudaGetSymbolAddress((void**)&geD, g_eDst);
    cudaGetSymbolAddress((void**)&geD3, g_eDst3);
    cudaGetSymbolAddress((void**)&gtot3, g_tot3);
    cudaGetSymbolAddress((void**)&gpadE3, g_padE3);
    cudaGetSymbolAddress((void**)&gtiles3, g_tiles3);

    int *geS, *geS3;
    cudaGetSymbolAddress((void**)&geS, g_eSrc);
    cudaGetSymbolAddress((void**)&geS3, g_eSrc3);

    cudaFuncSetAttribute(k_mma_gemm, cudaFuncAttributeMaxDynamicSharedMemorySize, SMEM_GEMM);
    cudaFuncSetAttribute(k_mma_ab,   cudaFuncAttributeMaxDynamicSharedMemorySize, SMEM_GEMM);
    cudaFuncSetAttribute(k_mma_edge, cudaFuncAttributeMaxDynamicSharedMemorySize, SMEM_EDGE);

    auto W = [&](int m) { return gw16 + (size_t)m * D * D; };

    const int ND = N_NODES * D;

    k_init<<<ND / 256, 256>>>(x);
    k_mask<<<NSEL / 256, 256>>>(sel);
    k_hist<<<E_EDGES / 256, 256>>>(dst);
    {
        dim3 grid(1024, NMAT);
        k_prep16<<<grid, 256>>>(conv_W1, conv_W2, ffn_W1, ffn_W2, gw16);
    }
    k_scan<<<1, 1024>>>(gcnt, gcur, nullptr);
    k_scan<<<1, 1024>>>(gcnt3, gcur3, gtot3);
    k_scatter<<<E_EDGES / 256, 256>>>(src, dst);
    k_pad<<<1, 256>>>();

    dim3 ggemm(D / BN, N_NODES / BM);        // (4, 64)
    dim3 gffn(D / BN, NSEL / BM);            // (4, 16)
    dim3 gab(2 * D / BN, N_NODES / BM);      // (8, 64)
    dim3 gedge(D / BN, E_EDGES / BM);        // (4, 1024)

    for (int l = 0; l < L_LAYERS; l++) {
        if (l == 0)
            k_lnc<<<N_NODES, 128>>>(0, conv_b2, ln1_g, ln1_b, gh16);
        else
            k_lnc<<<N_NODES, 128>>>(1, conv_b2 + (size_t)(l - 1) * D, ln1_g, ln1_b, gh16);
        k_mma_ab<<<gab, 256, SMEM_GEMM>>>(gh16, W(l * 3 + 0),
                                          conv_b1 + (size_t)l * D, ga16, gb16);
        if (l < 2) {
            k_zbuild<<<E_EDGES / 8, 256>>>(geD, geS, nullptr);
            k_mma_edge<<<gedge, 256, SMEM_EDGE>>>(W(l * 3 + 2),
                                                  conv_b2 + (size_t)l * D, gagg,
                                                  geD, nullptr);
        } else {
            k_zbuild<<<E_EDGES / 8, 256>>>(geD3, geS3, gpadE3);
            k_mma_edge<<<gedge, 256, SMEM_EDGE>>>(W(l * 3 + 2),
                                                  conv_b2 + (size_t)l * D, gagg,
                                                  geD3, gtiles3);
        }
    }

    // selected-rows tail: combine layer-3 agg + LN2 (compact), FFN, write d_out
    k_lnc_sel<<<NSEL, 128>>>(sel, conv_b2 + (size_t)2 * D, ln2_g, ln2_b, gh16);
    k_mma_gemm<<<gffn, 256, SMEM_GEMM>>>(gh16, W(9), ffn_b1, nullptr,
                                         nullptr, gt16, 1);
    k_mma_gemm<<<gffn, 256, SMEM_GEMM>>>(gt16, W(10), ffn_b2, gres,
                                         out, nullptr, 0);
}

// round 15
// speedup vs baseline: 1.6864x; 1.0238x over previous
#include <cuda_runtime.h>
#include <cuda_fp16.h>
#include <cstdint>
#include <cfloat>

// Problem constants (fixed shapes)
constexpr int N_NODES = 8192;
constexpr int D = 512;
constexpr int E_EDGES = 131072;
constexpr int B_GR = 16;
constexpr int NPG = 512;
constexpr int S_SEL = 128;
constexpr int L_LAYERS = 3;
constexpr int NSEL = B_GR * S_SEL;   // 2048 selected rows

// GEMM tiling (proven shape)
constexpr int BM = 128;
constexpr int BN = 128;
constexpr int BK = 64;
constexpr int NCH = D / BK;
constexpr int NMAT = 11;

constexpr int ROWB = 144;
constexpr int SA = 0;
constexpr int SW = 18432;
constexpr int STAGE = 36864;
constexpr int NSTG = 3;
constexpr int SM_IDX = NSTG * STAGE;
constexpr int SMEM_GEMM = NSTG * STAGE;
constexpr int SMEM_EDGE = NSTG * STAGE + 512;
constexpr int TPAD = 132;

// -------- static device scratch --------
__device__ float    g_x[N_NODES * D];
__device__ unsigned g_agg[N_NODES * D];
__device__ __align__(16) __half g_h16[N_NODES * D];
__device__ __align__(16) __half g_t16[N_NODES * D];
__device__ __align__(16) __half g_A16[N_NODES * D];
__device__ __align__(16) __half g_B16[N_NODES * D];
__device__ __align__(16) __half g_Z[(size_t)E_EDGES * D];
__device__ __align__(16) __half g_W16[(size_t)NMAT * D * D];
__device__ float    g_res[NSEL * D];        // compact residual for FFN
// edge sort / filter scratch
__device__ int g_cnt[N_NODES], g_cur[N_NODES];
__device__ int g_cnt3[N_NODES], g_cur3[N_NODES];
__device__ int g_selmask[N_NODES];
__device__ int g_eDst[E_EDGES], g_eSrc[E_EDGES];
__device__ int g_eDst3[E_EDGES], g_eSrc3[E_EDGES];
__device__ int g_tot3;
__device__ int g_padE3;
__device__ int g_tiles3;

// ---------------- helpers ----------------
__device__ __forceinline__ unsigned fenc(float f) {
    unsigned b = __float_as_uint(f);
    return (b & 0x80000000u) ? ~b : (b | 0x80000000u);
}
__device__ __forceinline__ float fdec(unsigned u) {
    unsigned b = (u & 0x80000000u) ? (u & 0x7fffffffu) : ~u;
    return __uint_as_float(b);
}
__device__ __forceinline__ uint32_t smem_u32(const void* p) {
    uint32_t a;
    asm("{ .reg .u64 t; cvta.to.shared.u64 t, %1; cvt.u32.u64 %0, t; }" : "=r"(a) : "l"(p));
    return a;
}
__device__ __forceinline__ void cp16(uint32_t dst, const void* src) {
    asm volatile("cp.async.cg.shared.global [%0], [%1], 16;" :: "r"(dst), "l"(src) : "memory");
}
__device__ __forceinline__ void cp_commit() {
    asm volatile("cp.async.commit_group;" ::: "memory");
}
template <int N>
__device__ __forceinline__ void cp_wait() {
    asm volatile("cp.async.wait_group %0;" :: "n"(N) : "memory");
}
__device__ __forceinline__ void ldm_x4(uint32_t* r, uint32_t addr) {
    asm volatile("ldmatrix.sync.aligned.m8n8.x4.shared.b16 {%0,%1,%2,%3}, [%4];"
                 : "=r"(r[0]), "=r"(r[1]), "=r"(r[2]), "=r"(r[3]) : "r"(addr));
}
__device__ __forceinline__ void mma_h(float* d, const uint32_t* a, uint32_t b0, uint32_t b1) {
    asm volatile(
        "mma.sync.aligned.m16n8k16.row.col.f32.f16.f16.f32 "
        "{%0,%1,%2,%3}, {%4,%5,%6,%7}, {%8,%9}, {%0,%1,%2,%3};"
        : "+f"(d[0]), "+f"(d[1]), "+f"(d[2]), "+f"(d[3])
        : "r"(a[0]), "r"(a[1]), "r"(a[2]), "r"(a[3]), "r"(b0), "r"(b1));
}
__device__ __forceinline__ void cp_rows128(uint32_t sbase, const __half* base, int k0, int tid) {
    #pragma unroll
    for (int i = 0; i < 4; i++) {
        int tx = tid + i * 256;
        int row = tx >> 3, seg = tx & 7;
        cp16(sbase + row * ROWB + seg * 16, base + (size_t)row * D + k0 + seg * 8);
    }
}

// ================= prep kernels =================
// zero agg + sort scratch (x copy folded into lnc0)
__global__ void k_init() {
    int i = blockIdx.x * 256 + threadIdx.x;
    g_agg[i] = 0u;
    if (i < N_NODES) { g_cnt[i] = 0; g_cnt3[i] = 0; g_selmask[i] = 0; }
}

__global__ void k_mask(const int* __restrict__ sel) {
    int i = blockIdx.x * 256 + threadIdx.x;   // 0..2047
    int node = (i >> 7) * NPG + sel[i];
    g_selmask[node] = 1;
}

__global__ void k_hist(const int* __restrict__ dst) {
    int e = blockIdx.x * 256 + threadIdx.x;
    int d = dst[e];
    atomicAdd(&g_cnt[d], 1);
    if (g_selmask[d]) atomicAdd(&g_cnt3[d], 1);
}

// both exclusive scans (cnt->cur, cnt3->cur3 + tot3) in one block of 1024 threads.
__device__ __forceinline__ void scan_one(const int* cnt, int* cur, int* tot, int* wsum) {
    int t = threadIdx.x;
    int base = t * 8;
    int v[8];
    int s = 0;
    #pragma unroll
    for (int i = 0; i < 8; i++) { v[i] = cnt[base + i]; s += v[i]; }
    int lane = t & 31, wid = t >> 5;
    int ps = s;
    #pragma unroll
    for (int o = 1; o < 32; o <<= 1) {
        int n = __shfl_up_sync(0xffffffffu, ps, o);
        if (lane >= o) ps += n;
    }
    if (lane == 31) wsum[wid] = ps;
    __syncthreads();
    if (wid == 0) {
        int ws = wsum[lane];
        #pragma unroll
        for (int o = 1; o < 32; o <<= 1) {
            int n = __shfl_up_sync(0xffffffffu, ws, o);
            if (lane >= o) ws += n;
        }
        wsum[lane] = ws;
    }
    __syncthreads();
    int run = ps - s + (wid > 0 ? wsum[wid - 1] : 0);
    #pragma unroll
    for (int i = 0; i < 8; i++) { cur[base + i] = run; run += v[i]; }
    if (tot && t == 1023) *tot = run;
}
__global__ __launch_bounds__(1024) void k_scan2() {
    __shared__ int wsum[32];
    scan_one(g_cnt, g_cur, nullptr, wsum);
    __syncthreads();
    scan_one(g_cnt3, g_cur3, &g_tot3, wsum);
}

__global__ void k_scatter(const int* __restrict__ src, const int* __restrict__ dst) {
    int e = blockIdx.x * 256 + threadIdx.x;
    int d = dst[e], sr = src[e];
    int p = atomicAdd(&g_cur[d], 1);
    g_eDst[p] = d;
    g_eSrc[p] = sr;
    if (g_selmask[d]) {
        int p3 = atomicAdd(&g_cur3[d], 1);
        g_eDst3[p3] = d;
        g_eSrc3[p3] = sr;
    }
}

__global__ __launch_bounds__(256) void k_pad() {
    int tot = g_tot3;
    int pad = (tot + 127) & ~127;
    if (pad > E_EDGES) pad = E_EDGES;
    if (tot > 0) {
        int ld = g_eDst3[tot - 1], ls = g_eSrc3[tot - 1];
        for (int i = tot + threadIdx.x; i < pad; i += 256) {
            g_eDst3[i] = ld;
            g_eSrc3[i] = ls;
        }
    }
    if (threadIdx.x == 0) { g_padE3 = pad; g_tiles3 = pad / BM; }
}

// fp16 weight prep, coalesced via 32x32 smem tile transpose.
// grid(16, 16, NMAT): block (bx=k-tile, by=n-tile, m). 256 threads.
__global__ __launch_bounds__(256) void k_prep16t(const float* __restrict__ W1,
                                                 const float* __restrict__ W2,
                                                 const float* __restrict__ fW1,
                                                 const float* __restrict__ fW2,
                                                 __half* __restrict__ img) {
    __shared__ float T[32][33];
    int m = blockIdx.z;
    int k0 = blockIdx.x * 32, n0 = blockIdx.y * 32;
    int tx = threadIdx.x & 31, ty = threadIdx.x >> 5;   // ty 0..7

    int l = m / 3, r = m % 3;
    const float* baseW1 = W1 + (size_t)l * 2 * D * D;

    #pragma unroll
    for (int i = 0; i < 4; i++) {
        int k = k0 + ty + i * 8, n = n0 + tx;
        float w;
        if (m < 9) {
            if (r == 0)      w = baseW1[(size_t)k * D + n] - baseW1[(size_t)(D + k) * D + n];
            else if (r == 1) w = baseW1[(size_t)(D + k) * D + n];
            else             w = W2[((size_t)l * D + k) * D + n];
        } else if (m == 9)   w = fW1[(size_t)k * D + n];
        else                 w = fW2[(size_t)k * D + n];
        T[ty + i * 8][tx] = w;
    }
    __syncthreads();
    __half* dst = img + (size_t)m * D * D;
    #pragma unroll
    for (int i = 0; i < 4; i++) {
        int n = n0 + ty + i * 8, k = k0 + tx;
        dst[(size_t)n * D + k] = __float2half(T[tx][ty + i * 8]);
    }
}

// fused combine (optional) + LayerNorm -> fp16 (all nodes).
// xin != nullptr (layer 0): read input x and write the residual copy to g_x.
__global__ __launch_bounds__(128) void k_lnc(const float* __restrict__ xin,
                                             int useAgg,
                                             const float* __restrict__ b2,
                                             const float* __restrict__ gamma,
                                             const float* __restrict__ beta,
                                             __half* __restrict__ out) {
    __shared__ float red[8];
    int row = blockIdx.x;
    int t = threadIdx.x;
    size_t base = (size_t)row * D + t * 4;
    float4 v;
    if (xin) {
        v = *(const float4*)(xin + base);
        *(float4*)(g_x + base) = v;
    } else {
        v = *(const float4*)(g_x + base);
    }
    if (useAgg) {
        uint4 u = *(const uint4*)(g_agg + base);
        *(uint4*)(g_agg + base) = make_uint4(0u, 0u, 0u, 0u);
        float4 bv = ((const float4*)b2)[t];
        float m0 = u.x ? fdec(u.x) + bv.x : 0.f;
        float m1 = u.y ? fdec(u.y) + bv.y : 0.f;
        float m2 = u.z ? fdec(u.z) + bv.z : 0.f;
        float m3 = u.w ? fdec(u.w) + bv.w : 0.f;
        v.x += fmaxf(m0, 0.f); v.y += fmaxf(m1, 0.f);
        v.z += fmaxf(m2, 0.f); v.w += fmaxf(m3, 0.f);
        *(float4*)(g_x + base) = v;
    }
    float s = v.x + v.y + v.z + v.w;
    #pragma unroll
    for (int o = 16; o > 0; o >>= 1) s += __shfl_xor_sync(0xffffffffu, s, o);
    if ((t & 31) == 0) red[t >> 5] = s;
    __syncthreads();
    if (t == 0) red[4] = red[0] + red[1] + red[2] + red[3];
    __syncthreads();
    float mu = red[4] * (1.0f / D);
    __syncthreads();
    float dx = v.x - mu, dy = v.y - mu, dz = v.z - mu, dw = v.w - mu;
    float q = dx * dx + dy * dy + dz * dz + dw * dw;
    #pragma unroll
    for (int o = 16; o > 0; o >>= 1) q += __shfl_xor_sync(0xffffffffu, q, o);
    if ((t & 31) == 0) red[t >> 5] = q;
    __syncthreads();
    if (t == 0) red[4] = red[0] + red[1] + red[2] + red[3];
    __syncthreads();
    float rstd = rsqrtf(red[4] * (1.0f / D) + 1e-5f);
    float4 g4 = ((const float4*)gamma)[t];
    float4 b4 = ((const float4*)beta)[t];
    __half2 h0 = __floats2half2_rn(dx * rstd * g4.x + b4.x, dy * rstd * g4.y + b4.y);
    __half2 h1 = __floats2half2_rn(dz * rstd * g4.z + b4.z, dw * rstd * g4.w + b4.w);
    *(uint2*)(out + base) = make_uint2(*(uint32_t*)&h0, *(uint32_t*)&h1);
}

// selected-rows combine + LN2 -> compact fp16 + compact fp32 residual (agg read-only).
__global__ __launch_bounds__(128) void k_lnc_sel(const int* __restrict__ sel,
                                                 const float* __restrict__ b2,
                                                 const float* __restrict__ gamma,
                                                 const float* __restrict__ beta,
                                                 __half* __restrict__ hout) {
    __shared__ float red[8];
    int r = blockIdx.x;
    int t = threadIdx.x;
    int node = (r >> 7) * NPG + sel[r];
    size_t base = (size_t)node * D + t * 4;
    float4 v = *(const float4*)(g_x + base);
    uint4 u = *(const uint4*)(g_agg + base);
    float4 bv = ((const float4*)b2)[t];
    float m0 = u.x ? fdec(u.x) + bv.x : 0.f;
    float m1 = u.y ? fdec(u.y) + bv.y : 0.f;
    float m2 = u.z ? fdec(u.z) + bv.z : 0.f;
    float m3 = u.w ? fdec(u.w) + bv.w : 0.f;
    v.x += fmaxf(m0, 0.f); v.y += fmaxf(m1, 0.f);
    v.z += fmaxf(m2, 0.f); v.w += fmaxf(m3, 0.f);
    *(float4*)(g_res + (size_t)r * D + t * 4) = v;

    float s = v.x + v.y + v.z + v.w;
    #pragma unroll
    for (int o = 16; o > 0; o >>= 1) s += __shfl_xor_sync(0xffffffffu, s, o);
    if ((t & 31) == 0) red[t >> 5] = s;
    __syncthreads();
    if (t == 0) red[4] = red[0] + red[1] + red[2] + red[3];
    __syncthreads();
    float mu = red[4] * (1.0f / D);
    __syncthreads();
    float dx = v.x - mu, dy = v.y - mu, dz = v.z - mu, dw = v.w - mu;
    float q = dx * dx + dy * dy + dz * dz + dw * dw;
    #pragma unroll
    for (int o = 16; o > 0; o >>= 1) q += __shfl_xor_sync(0xffffffffu, q, o);
    if ((t & 31) == 0) red[t >> 5] = q;
    __syncthreads();
    if (t == 0) red[4] = red[0] + red[1] + red[2] + red[3];
    __syncthreads();
    float rstd = rsqrtf(red[4] * (1.0f / D) + 1e-5f);
    float4 g4 = ((const float4*)gamma)[t];
    float4 b4 = ((const float4*)beta)[t];
    __half2 h0 = __floats2half2_rn(dx * rstd * g4.x + b4.x, dy * rstd * g4.y + b4.y);
    __half2 h1 = __floats2half2_rn(dz * rstd * g4.z + b4.z, dw * rstd * g4.w + b4.w);
    *(uint2*)(hout + (size_t)r * D + t * 4) = make_uint2(*(uint32_t*)&h0, *(uint32_t*)&h1);
}

// Z build over an edge list (sorted, possibly filtered+padded)
__global__ __launch_bounds__(256) void k_zbuild(const int* __restrict__ eD,
                                                const int* __restrict__ eS,
                                                const int* __restrict__ dynCount) {
    int e = blockIdx.x * 8 + (threadIdx.x >> 5);
    if (dynCount && e >= *dynCount) return;
    int sg = threadIdx.x & 31;
    int de = eD[e], se = eS[e];
    const uint4* a = (const uint4*)(g_A16 + (size_t)de * D);
    const uint4* b = (const uint4*)(g_B16 + (size_t)se * D);
    uint4* z = (uint4*)(g_Z + (size_t)e * D);
    const __half2 zero2 = __floats2half2_rn(0.f, 0.f);
    #pragma unroll
    for (int i = 0; i < 2; i++) {
        int s = sg + i * 32;
        uint4 av = a[s], bv = b[s];
        uint4 r;
        __half2 h;
        h = __hmax2(__hadd2(*(__half2*)&av.x, *(__half2*)&bv.x), zero2); r.x = *(uint32_t*)&h;
        h = __hmax2(__hadd2(*(__half2*)&av.y, *(__half2*)&bv.y), zero2); r.y = *(uint32_t*)&h;
        h = __hmax2(__hadd2(*(__half2*)&av.z, *(__half2*)&bv.z), zero2); r.z = *(uint32_t*)&h;
        h = __hmax2(__hadd2(*(__half2*)&av.w, *(__half2*)&bv.w), zero2); r.w = *(uint32_t*)&h;
        z[s] = r;
    }
}

// ================= dense fp16 GEMM (generic) =================
__global__ __launch_bounds__(256, 2) void k_mma_gemm(
    const __half* __restrict__ Ain,
    const __half* __restrict__ w,
    const float* __restrict__ bias,
    const float* __restrict__ res,
    float* __restrict__ out,
    __half* __restrict__ out16,
    int relu)
{
    extern __shared__ char smem[];
    int tid = threadIdx.x;
    int n0 = blockIdx.x * BN;
    int m0 = blockIdx.y * BM;
    int lane = tid & 31, wm = (tid >> 5) & 1, wn = tid >> 6;

    uint32_t s[NSTG];
    #pragma unroll
    for (int i = 0; i < NSTG; i++) s[i] = smem_u32(smem + i * STAGE);
    const __half* abase = Ain + (size_t)m0 * D;
    const __half* wbase = w + (size_t)n0 * D;
    uint32_t aoff = (uint32_t)(wm * 64 + (lane & 7) + ((lane >> 3) & 1) * 8) * ROWB
                  + ((lane >> 4) & 1) * 16;
    uint32_t boff = (uint32_t)(wn * 32 + (lane & 7) + ((lane >= 16) ? 8 : 0)) * ROWB
                  + ((lane >> 3) & 1) * 16;

    float acc[4][4][4] = {};

    cp_rows128(s[0] + SA, abase, 0, tid);
    cp_rows128(s[0] + SW, wbase, 0, tid);
    cp_commit();
    cp_rows128(s[1] + SA, abase, BK, tid);
    cp_rows128(s[1] + SW, wbase, BK, tid);
    cp_commit();
    cp_wait<1>();
    __syncthreads();

    for (int c = 0; c < NCH; c++) {
        uint32_t sc = s[c % NSTG];
        if (c + 2 < NCH) {
            uint32_t sn = s[(c + 2) % NSTG];
            cp_rows128(sn + SA, abase, (c + 2) * BK, tid);
            cp_rows128(sn + SW, wbase, (c + 2) * BK, tid);
            cp_commit();
        }
        #pragma unroll
        for (int kh = 0; kh < 4; kh++) {
            uint32_t bh[2][4];
            #pragma unroll
            for (int np = 0; np < 2; np++)
                ldm_x4(bh[np], sc + SW + boff + np * 16 * ROWB + kh * 32);
            #pragma unroll
            for (int mf = 0; mf < 4; mf++) {
                uint32_t ah[4];
                ldm_x4(ah, sc + SA + aoff + mf * 16 * ROWB + kh * 32);
                #pragma unroll
                for (int np = 0; np < 2; np++) {
                    #pragma unroll
                    for (int j = 0; j < 2; j++)
                        mma_h(acc[mf][np * 2 + j], ah, bh[np][2 * j], bh[np][2 * j + 1]);
                }
            }
        }
        if (c + 2 < NCH) cp_wait<1>();
        else if (c + 1 < NCH) cp_wait<0>();
        __syncthreads();
    }

    #pragma unroll
    for (int mf = 0; mf < 4; mf++) {
        int r0 = m0 + wm * 64 + mf * 16 + (lane >> 2);
        int colb = n0 + wn * 32 + 2 * (lane & 3);
        #pragma unroll
        for (int nf = 0; nf < 4; nf++) {
            int col = colb + nf * 8;
            float2 bv = bias ? *(const float2*)(bias + col) : make_float2(0.f, 0.f);
            float c0 = acc[mf][nf][0] + bv.x, c1 = acc[mf][nf][1] + bv.y;
            float c2 = acc[mf][nf][2] + bv.x, c3 = acc[mf][nf][3] + bv.y;
            if (relu) {
                c0 = fmaxf(c0, 0.f); c1 = fmaxf(c1, 0.f);
                c2 = fmaxf(c2, 0.f); c3 = fmaxf(c3, 0.f);
            }
            if (res) {
                float2 r1v = *(const float2*)(res + (size_t)r0 * D + col);
                float2 r2v = *(const float2*)(res + (size_t)(r0 + 8) * D + col);
                c0 += r1v.x; c1 += r1v.y; c2 += r2v.x; c3 += r2v.y;
            }
            if (out) {
                *(float2*)(out + (size_t)r0 * D + col) = make_float2(c0, c1);
                *(float2*)(out + (size_t)(r0 + 8) * D + col) = make_float2(c2, c3);
            }
            if (out16) {
                __half2 h0 = __floats2half2_rn(c0, c1);
                __half2 h1 = __floats2half2_rn(c2, c3);
                *(uint32_t*)(out16 + (size_t)r0 * D + col) = *(uint32_t*)&h0;
                *(uint32_t*)(out16 + (size_t)(r0 + 8) * D + col) = *(uint32_t*)&h1;
            }
        }
    }
}

// ================= merged A|B node GEMM =================
__global__ __launch_bounds__(256, 2) void k_mma_ab(
    const __half* __restrict__ Hm,
    const __half* __restrict__ w,
    const float* __restrict__ b1,
    __half* __restrict__ A16,
    __half* __restrict__ B16)
{
    extern __shared__ char smem[];
    int tid = threadIdx.x;
    int n0 = blockIdx.x * BN;
    int m0 = blockIdx.y * BM;
    int lane = tid & 31, wm = (tid >> 5) & 1, wn = tid >> 6;

    bool isA = (n0 < D);
    __half* dstbuf = isA ? A16 : B16;
    int cbase = isA ? 0 : D;
    const float* bias = isA ? b1 : nullptr;

    uint32_t s[NSTG];
    #pragma unroll
    for (int i = 0; i < NSTG; i++) s[i] = smem_u32(smem + i * STAGE);
    const __half* abase = Hm + (size_t)m0 * D;
    const __half* wbase = w + (size_t)n0 * D;
    uint32_t aoff = (uint32_t)(wm * 64 + (lane & 7) + ((lane >> 3) & 1) * 8) * ROWB
                  + ((lane >> 4) & 1) * 16;
    uint32_t boff = (uint32_t)(wn * 32 + (lane & 7) + ((lane >= 16) ? 8 : 0)) * ROWB
                  + ((lane >> 3) & 1) * 16;

    float acc[4][4][4] = {};

    cp_rows128(s[0] + SA, abase, 0, tid);
    cp_rows128(s[0] + SW, wbase, 0, tid);
    cp_commit();
    cp_rows128(s[1] + SA, abase, BK, tid);
    cp_rows128(s[1] + SW, wbase, BK, tid);
    cp_commit();
    cp_wait<1>();
    __syncthreads();

    for (int c = 0; c < NCH; c++) {
        uint32_t sc = s[c % NSTG];
        if (c + 2 < NCH) {
            uint32_t sn = s[(c + 2) % NSTG];
            cp_rows128(sn + SA, abase, (c + 2) * BK, tid);
            cp_rows128(sn + SW, wbase, (c + 2) * BK, tid);
            cp_commit();
        }
        #pragma unroll
        for (int kh = 0; kh < 4; kh++) {
            uint32_t bh[2][4];
            #pragma unroll
            for (int np = 0; np < 2; np++)
                ldm_x4(bh[np], sc + SW + boff + np * 16 * ROWB + kh * 32);
            #pragma unroll
            for (int mf = 0; mf < 4; mf++) {
                uint32_t ah[4];
                ldm_x4(ah, sc + SA + aoff + mf * 16 * ROWB + kh * 32);
                #pragma unroll
                for (int np = 0; np < 2; np++) {
                    #pragma unroll
                    for (int j = 0; j < 2; j++)
                        mma_h(acc[mf][np * 2 + j], ah, bh[np][2 * j], bh[np][2 * j + 1]);
                }
            }
        }
        if (c + 2 < NCH) cp_wait<1>();
        else if (c + 1 < NCH) cp_wait<0>();
        __syncthreads();
    }

    #pragma unroll
    for (int mf = 0; mf < 4; mf++) {
        int r0 = m0 + wm * 64 + mf * 16 + (lane >> 2);
        int colb = n0 + wn * 32 + 2 * (lane & 3);
        #pragma unroll
        for (int nf = 0; nf < 4; nf++) {
            int col = colb + nf * 8;
            float2 bv = bias ? *(const float2*)(bias + col) : make_float2(0.f, 0.f);
            float c0 = acc[mf][nf][0] + bv.x, c1 = acc[mf][nf][1] + bv.y;
            float c2 = acc[mf][nf][2] + bv.x, c3 = acc[mf][nf][3] + bv.y;
            int dc = col - cbase;
            __half2 h0 = __floats2half2_rn(c0, c1);
            __half2 h1 = __floats2half2_rn(c2, c3);
            *(uint32_t*)(dstbuf + (size_t)r0 * D + dc) = *(uint32_t*)&h0;
            *(uint32_t*)(dstbuf + (size_t)(r0 + 8) * D + dc) = *(uint32_t*)&h1;
        }
    }
}

// ================= edge GEMM: Z(sorted list) @ W2 -> smem segment-reduce -> atomicMax =================
__global__ __launch_bounds__(256, 2) void k_mma_edge(
    const __half* __restrict__ w16,
    const float* __restrict__ b2,
    unsigned* __restrict__ agg,
    const int* __restrict__ eD,
    const int* __restrict__ tileLimit)
{
    extern __shared__ char smem[];
    int e0 = blockIdx.y * BM;
    if (tileLimit && blockIdx.y >= *tileLimit) return;
    int tid = threadIdx.x;
    int n0 = blockIdx.x * BN;
    int lane = tid & 31, wm = (tid >> 5) & 1, wn = tid >> 6;

    int* sDst = (int*)(smem + SM_IDX);
    if (tid < 128) sDst[tid] = eD[e0 + tid];

    uint32_t s[NSTG];
    #pragma unroll
    for (int i = 0; i < NSTG; i++) s[i] = smem_u32(smem + i * STAGE);
    const __half* abase = g_Z + (size_t)e0 * D;
    const __half* wbase = w16 + (size_t)n0 * D;
    uint32_t aoff = (uint32_t)(wm * 64 + (lane & 7) + ((lane >> 3) & 1) * 8) * ROWB
                  + ((lane >> 4) & 1) * 16;
    uint32_t boff = (uint32_t)(wn * 32 + (lane & 7) + ((lane >= 16) ? 8 : 0)) * ROWB
                  + ((lane >> 3) & 1) * 16;

    float acc[4][4][4] = {};

    cp_rows128(s[0] + SA, abase, 0, tid);
    cp_rows128(s[0] + SW, wbase, 0, tid);
    cp_commit();
    cp_rows128(s[1] + SA, abase, BK, tid);
    cp_rows128(s[1] + SW, wbase, BK, tid);
    cp_commit();
    cp_wait<1>();
    __syncthreads();

    for (int c = 0; c < NCH; c++) {
        uint32_t sc = s[c % NSTG];
        if (c + 2 < NCH) {
            uint32_t sn = s[(c + 2) % NSTG];
            cp_rows128(sn + SA, abase, (c + 2) * BK, tid);
            cp_rows128(sn + SW, wbase, (c + 2) * BK, tid);
            cp_commit();
        }
        #pragma unroll
        for (int kh = 0; kh < 4; kh++) {
            uint32_t bh[2][4];
            #pragma unroll
            for (int np = 0; np < 2; np++)
                ldm_x4(bh[np], sc + SW + boff + np * 16 * ROWB + kh * 32);
            #pragma unroll
            for (int mf = 0; mf < 4; mf++) {
                uint32_t ah[4];
                ldm_x4(ah, sc + SA + aoff + mf * 16 * ROWB + kh * 32);
                #pragma unroll
                for (int np = 0; np < 2; np++) {
                    #pragma unroll
                    for (int j = 0; j < 2; j++)
                        mma_h(acc[mf][np * 2 + j], ah, bh[np][2 * j], bh[np][2 * j + 1]);
                }
            }
        }
        if (c + 2 < NCH) cp_wait<1>();
        else if (c + 1 < NCH) cp_wait<0>();
        __syncthreads();
    }

    // epilogue: acc -> smem f32 tile, segment-reduce by sorted dst, gated atomics
    float* T = (float*)smem;
    #pragma unroll
    for (int mf = 0; mf < 4; mf++) {
        int r0 = wm * 64 + mf * 16 + (lane >> 2);
        int cl = wn * 32 + 2 * (lane & 3);
        #pragma unroll
        for (int nf = 0; nf < 4; nf++) {
            *(float2*)&T[r0 * TPAD + cl + nf * 8] =
                make_float2(acc[mf][nf][0], acc[mf][nf][1]);
            *(float2*)&T[(r0 + 8) * TPAD + cl + nf * 8] =
                make_float2(acc[mf][nf][2], acc[mf][nf][3]);
        }
    }
    __syncthreads();

    {
        int col = tid & 127, half = tid >> 7;
        float thr = -b2[n0 + col];
        unsigned* aggcol = agg + n0 + col;
        int rbeg = half * 64, rend = rbeg + 64;
        int prevd = sDst[rbeg];
        float run = -FLT_MAX;
        for (int r = rbeg; r < rend; r++) {
            int d = sDst[r];
            float v = T[r * TPAD + col];
            if (d != prevd) {
                if (run > thr) atomicMax(aggcol + (size_t)prevd * D, fenc(run));
                prevd = d;
                run = v;
            } else {
                run = fmaxf(run, v);
            }
        }
        if (run > thr) atomicMax(aggcol + (size_t)prevd * D, fenc(run));
    }
}

// ================= host launcher =================
extern "C" void kernel_launch(void* const* d_in, const int* in_sizes, int n_in,
                              void* d_out, int out_size) {
    const float* x       = (const float*)d_in[0];
    const int*   eidx    = (const int*)d_in[1];
    const int*   sel     = (const int*)d_in[2];
    const float* conv_W1 = (const float*)d_in[4];
    const float* conv_b1 = (const float*)d_in[5];
    const float* conv_W2 = (const float*)d_in[6];
    const float* conv_b2 = (const float*)d_in[7];
    const float* ln1_g   = (const float*)d_in[8];
    const float* ln1_b   = (const float*)d_in[9];
    const float* ln2_g   = (const float*)d_in[10];
    const float* ln2_b   = (const float*)d_in[11];
    const float* ffn_W1  = (const float*)d_in[12];
    const float* ffn_b1  = (const float*)d_in[13];
    const float* ffn_W2  = (const float*)d_in[14];
    const float* ffn_b2  = (const float*)d_in[15];
    float* out = (float*)d_out;

    const int* src = eidx;
    const int* dst = eidx + E_EDGES;

    float *gres;
    unsigned* gagg;
    __half *gh16, *gt16, *ga16, *gb16, *gw16;
    int *geD, *geD3, *geS, *geS3, *gpadE3, *gtiles3;
    cudaGetSymbolAddress((void**)&gres, g_res);
    cudaGetSymbolAddress((void**)&gagg, g_agg);
    cudaGetSymbolAddress((void**)&gh16, g_h16);
    cudaGetSymbolAddress((void**)&gt16, g_t16);
    cudaGetSymbolAddress((void**)&ga16, g_A16);
    cudaGetSymbolAddress((void**)&gb16, g_B16);
    cudaGetSymbolAddress((void**)&gw16, g_W16);
    cudaGetSymbolAddress((void**)&geD, g_eDst);
    cudaGetSymbolAddress((void**)&geD3, g_eDst3);
    cudaGetSymbolAddress((void**)&geS, g_eSrc);
    cudaGetSymbolAddress((void**)&geS3, g_eSrc3);
    cudaGetSymbolAddress((void**)&gpadE3, g_padE3);
    cudaGetSymbolAddress((void**)&gtiles3, g_tiles3);

    cudaFuncSetAttribute(k_mma_gemm, cudaFuncAttributeMaxDynamicSharedMemorySize, SMEM_GEMM);
    cudaFuncSetAttribute(k_mma_ab,   cudaFuncAttributeMaxDynamicSharedMemorySize, SMEM_GEMM);
    cudaFuncSetAttribute(k_mma_edge, cudaFuncAttributeMaxDynamicSharedMemorySize, SMEM_EDGE);

    auto W = [&](int m) { return gw16 + (size_t)m * D * D; };

    const int ND = N_NODES * D;

    k_init<<<ND / 256, 256>>>();
    k_mask<<<NSEL / 256, 256>>>(sel);
    k_hist<<<E_EDGES / 256, 256>>>(dst);
    {
        dim3 grid(16, 16, NMAT);
        k_prep16t<<<grid, 256>>>(conv_W1, conv_W2, ffn_W1, ffn_W2, gw16);
    }
    k_scan2<<<1, 1024>>>();
    k_scatter<<<E_EDGES / 256, 256>>>(src, dst);
    k_pad<<<1, 256>>>();

    dim3 gffn(D / BN, NSEL / BM);            // (4, 16)
    dim3 gab(2 * D / BN, N_NODES / BM);      // (8, 64)
    dim3 gedge(D / BN, E_EDGES / BM);        // (4, 1024)

    for (int l = 0; l < L_LAYERS; l++) {
        if (l == 0)
            k_lnc<<<N_NODES, 128>>>(x, 0, conv_b2, ln1_g, ln1_b, gh16);
        else
            k_lnc<<<N_NODES, 128>>>(nullptr, 1, conv_b2 + (size_t)(l - 1) * D,
                                    ln1_g, ln1_b, gh16);
        k_mma_ab<<<gab, 256, SMEM_GEMM>>>(gh16, W(l * 3 + 0),
                                          conv_b1 + (size_t)l * D, ga16, gb16);
        if (l < 2) {
            k_zbuild<<<E_EDGES / 8, 256>>>(geD, geS, nullptr);
            k_mma_edge<<<gedge, 256, SMEM_EDGE>>>(W(l * 3 + 2),
                                                  conv_b2 + (size_t)l * D, gagg,
                                                  geD, nullptr);
        } else {
            k_zbuild<<<E_EDGES / 8, 256>>>(geD3, geS3, gpadE3);
            k_mma_edge<<<gedge, 256, SMEM_EDGE>>>(W(l * 3 + 2),
                                                  conv_b2 + (size_t)l * D, gagg,
                                                  geD3, gtiles3);
        }
    }

    // selected-rows tail: combine layer-3 agg + LN2 (compact), FFN, write d_out
    k_lnc_sel<<<NSEL, 128>>>(sel, conv_b2 + (size_t)2 * D, ln2_g, ln2_b, gh16);
    k_mma_gemm<<<gffn, 256, SMEM_GEMM>>>(gh16, W(9), ffn_b1, nullptr,
                                         nullptr, gt16, 1);
    k_mma_gemm<<<gffn, 256, SMEM_GEMM>>>(gt16, W(10), ffn_b2, gres,
                                         out, nullptr, 0);
}

// round 16
// speedup vs baseline: 1.6879x; 1.0009x over previous
#include <cuda_runtime.h>
#include <cuda_fp16.h>
#include <cstdint>
#include <cfloat>

// Problem constants (fixed shapes)
constexpr int N_NODES = 8192;
constexpr int D = 512;
constexpr int E_EDGES = 131072;
constexpr int B_GR = 16;
constexpr int NPG = 512;
constexpr int S_SEL = 128;
constexpr int L_LAYERS = 3;
constexpr int NSEL = B_GR * S_SEL;   // 2048 selected rows

// GEMM tiling (proven shape)
constexpr int BM = 128;
constexpr int BN = 128;
constexpr int BK = 64;
constexpr int NCH = D / BK;
constexpr int NMAT = 11;

constexpr int ROWB = 144;
constexpr int SA = 0;
constexpr int SW = 18432;
constexpr int STAGE = 36864;
constexpr int NSTG = 3;
constexpr int SM_IDX = NSTG * STAGE;
constexpr int SMEM_GEMM = NSTG * STAGE;
constexpr int SMEM_EDGE = NSTG * STAGE + 512;
constexpr int TPAD = 132;

// -------- static device scratch --------
__device__ float    g_x[N_NODES * D];
__device__ unsigned g_agg[N_NODES * D];
__device__ __align__(16) __half g_h16[N_NODES * D];
__device__ __align__(16) __half g_t16[N_NODES * D];
__device__ __align__(16) __half g_A16[N_NODES * D];
__device__ __align__(16) __half g_B16[N_NODES * D];
__device__ __align__(16) __half g_Z[(size_t)E_EDGES * D];
__device__ __align__(16) __half g_W16[(size_t)NMAT * D * D];
__device__ float    g_res[NSEL * D];        // compact residual for FFN
// edge sort / filter scratch
__device__ int g_cnt[N_NODES], g_cur[N_NODES];
__device__ int g_cnt3[N_NODES], g_cur3[N_NODES];
__device__ int g_selmask[N_NODES];
__device__ int g_eDst[E_EDGES], g_eSrc[E_EDGES];
__device__ int g_eDst3[E_EDGES], g_eSrc3[E_EDGES];
__device__ int g_tot3;
__device__ int g_padE3;
__device__ int g_tiles3;

// ---------------- helpers ----------------
__device__ __forceinline__ unsigned fenc(float f) {
    unsigned b = __float_as_uint(f);
    return (b & 0x80000000u) ? ~b : (b | 0x80000000u);
}
__device__ __forceinline__ float fdec(unsigned u) {
    unsigned b = (u & 0x80000000u) ? (u & 0x7fffffffu) : ~u;
    return __uint_as_float(b);
}
__device__ __forceinline__ uint32_t smem_u32(const void* p) {
    uint32_t a;
    asm("{ .reg .u64 t; cvta.to.shared.u64 t, %1; cvt.u32.u64 %0, t; }" : "=r"(a) : "l"(p));
    return a;
}
__device__ __forceinline__ void cp16(uint32_t dst, const void* src) {
    asm volatile("cp.async.cg.shared.global [%0], [%1], 16;" :: "r"(dst), "l"(src) : "memory");
}
__device__ __forceinline__ void cp_commit() {
    asm volatile("cp.async.commit_group;" ::: "memory");
}
template <int N>
__device__ __forceinline__ void cp_wait() {
    asm volatile("cp.async.wait_group %0;" :: "n"(N) : "memory");
}
__device__ __forceinline__ void ldm_x4(uint32_t* r, uint32_t addr) {
    asm volatile("ldmatrix.sync.aligned.m8n8.x4.shared.b16 {%0,%1,%2,%3}, [%4];"
                 : "=r"(r[0]), "=r"(r[1]), "=r"(r[2]), "=r"(r[3]) : "r"(addr));
}
__device__ __forceinline__ void mma_h(float* d, const uint32_t* a, uint32_t b0, uint32_t b1) {
    asm volatile(
        "mma.sync.aligned.m16n8k16.row.col.f32.f16.f16.f32 "
        "{%0,%1,%2,%3}, {%4,%5,%6,%7}, {%8,%9}, {%0,%1,%2,%3};"
        : "+f"(d[0]), "+f"(d[1]), "+f"(d[2]), "+f"(d[3])
        : "r"(a[0]), "r"(a[1]), "r"(a[2]), "r"(a[3]), "r"(b0), "r"(b1));
}
__device__ __forceinline__ void cp_rows128(uint32_t sbase, const __half* base, int k0, int tid) {
    #pragma unroll
    for (int i = 0; i < 4; i++) {
        int tx = tid + i * 256;
        int row = tx >> 3, seg = tx & 7;
        cp16(sbase + row * ROWB + seg * 16, base + (size_t)row * D + k0 + seg * 8);
    }
}

// ================= prep kernels =================
// zero agg + sort scratch (x copy folded into lnc0)
__global__ void k_init() {
    int i = blockIdx.x * 256 + threadIdx.x;
    g_agg[i] = 0u;
    if (i < N_NODES) { g_cnt[i] = 0; g_cnt3[i] = 0; g_selmask[i] = 0; }
}

__global__ void k_mask(const int* __restrict__ sel) {
    int i = blockIdx.x * 256 + threadIdx.x;   // 0..2047
    int node = (i >> 7) * NPG + sel[i];
    g_selmask[node] = 1;
}

__global__ void k_hist(const int* __restrict__ dst) {
    int e = blockIdx.x * 256 + threadIdx.x;
    int d = dst[e];
    atomicAdd(&g_cnt[d], 1);
    if (g_selmask[d]) atomicAdd(&g_cnt3[d], 1);
}

// both exclusive scans (cnt->cur, cnt3->cur3 + tot3) in one block of 1024 threads.
__device__ __forceinline__ void scan_one(const int* cnt, int* cur, int* tot, int* wsum) {
    int t = threadIdx.x;
    int base = t * 8;
    int v[8];
    int s = 0;
    #pragma unroll
    for (int i = 0; i < 8; i++) { v[i] = cnt[base + i]; s += v[i]; }
    int lane = t & 31, wid = t >> 5;
    int ps = s;
    #pragma unroll
    for (int o = 1; o < 32; o <<= 1) {
        int n = __shfl_up_sync(0xffffffffu, ps, o);
        if (lane >= o) ps += n;
    }
    if (lane == 31) wsum[wid] = ps;
    __syncthreads();
    if (wid == 0) {
        int ws = wsum[lane];
        #pragma unroll
        for (int o = 1; o < 32; o <<= 1) {
            int n = __shfl_up_sync(0xffffffffu, ws, o);
            if (lane >= o) ws += n;
        }
        wsum[lane] = ws;
    }
    __syncthreads();
    int run = ps - s + (wid > 0 ? wsum[wid - 1] : 0);
    #pragma unroll
    for (int i = 0; i < 8; i++) { cur[base + i] = run; run += v[i]; }
    if (tot && t == 1023) *tot = run;
}
__global__ __launch_bounds__(1024) void k_scan2() {
    __shared__ int wsum[32];
    scan_one(g_cnt, g_cur, nullptr, wsum);
    __syncthreads();
    scan_one(g_cnt3, g_cur3, &g_tot3, wsum);
}

__global__ void k_scatter(const int* __restrict__ src, const int* __restrict__ dst) {
    int e = blockIdx.x * 256 + threadIdx.x;
    int d = dst[e], sr = src[e];
    int p = atomicAdd(&g_cur[d], 1);
    g_eDst[p] = d;
    g_eSrc[p] = sr;
    if (g_selmask[d]) {
        int p3 = atomicAdd(&g_cur3[d], 1);
        g_eDst3[p3] = d;
        g_eSrc3[p3] = sr;
    }
}

__global__ __launch_bounds__(256) void k_pad() {
    int tot = g_tot3;
    int pad = (tot + 127) & ~127;
    if (pad > E_EDGES) pad = E_EDGES;
    if (tot > 0) {
        int ld = g_eDst3[tot - 1], ls = g_eSrc3[tot - 1];
        for (int i = tot + threadIdx.x; i < pad; i += 256) {
            g_eDst3[i] = ld;
            g_eSrc3[i] = ls;
        }
    }
    if (threadIdx.x == 0) { g_padE3 = pad; g_tiles3 = pad / BM; }
}

// fp16 weight prep, coalesced via 32x32 smem tile transpose.
// grid(16, 16, NMAT): block (bx=k-tile, by=n-tile, m). 256 threads.
__global__ __launch_bounds__(256) void k_prep16t(const float* __restrict__ W1,
                                                 const float* __restrict__ W2,
                                                 const float* __restrict__ fW1,
                                                 const float* __restrict__ fW2,
                                                 __half* __restrict__ img) {
    __shared__ float T[32][33];
    int m = blockIdx.z;
    int k0 = blockIdx.x * 32, n0 = blockIdx.y * 32;
    int tx = threadIdx.x & 31, ty = threadIdx.x >> 5;   // ty 0..7

    int l = m / 3, r = m % 3;
    const float* baseW1 = W1 + (size_t)l * 2 * D * D;

    #pragma unroll
    for (int i = 0; i < 4; i++) {
        int k = k0 + ty + i * 8, n = n0 + tx;
        float w;
        if (m < 9) {
            if (r == 0)      w = baseW1[(size_t)k * D + n] - baseW1[(size_t)(D + k) * D + n];
            else if (r == 1) w = baseW1[(size_t)(D + k) * D + n];
            else             w = W2[((size_t)l * D + k) * D + n];
        } else if (m == 9)   w = fW1[(size_t)k * D + n];
        else                 w = fW2[(size_t)k * D + n];
        T[ty + i * 8][tx] = w;
    }
    __syncthreads();
    __half* dst = img + (size_t)m * D * D;
    #pragma unroll
    for (int i = 0; i < 4; i++) {
        int n = n0 + ty + i * 8, k = k0 + tx;
        dst[(size_t)n * D + k] = __float2half(T[tx][ty + i * 8]);
    }
}

// fused combine (optional) + LayerNorm -> fp16 (all nodes).
// xin != nullptr (layer 0): read input x and write the residual copy to g_x.
__global__ __launch_bounds__(128) void k_lnc(const float* __restrict__ xin,
                                             int useAgg,
                                             const float* __restrict__ b2,
                                             const float* __restrict__ gamma,
                                             const float* __restrict__ beta,
                                             __half* __restrict__ out) {
    __shared__ float red[8];
    int row = blockIdx.x;
    int t = threadIdx.x;
    size_t base = (size_t)row * D + t * 4;
    float4 v;
    if (xin) {
        v = *(const float4*)(xin + base);
        *(float4*)(g_x + base) = v;
    } else {
        v = *(const float4*)(g_x + base);
    }
    if (useAgg) {
        uint4 u = *(const uint4*)(g_agg + base);
        *(uint4*)(g_agg + base) = make_uint4(0u, 0u, 0u, 0u);
        float4 bv = ((const float4*)b2)[t];
        float m0 = u.x ? fdec(u.x) + bv.x : 0.f;
        float m1 = u.y ? fdec(u.y) + bv.y : 0.f;
        float m2 = u.z ? fdec(u.z) + bv.z : 0.f;
        float m3 = u.w ? fdec(u.w) + bv.w : 0.f;
        v.x += fmaxf(m0, 0.f); v.y += fmaxf(m1, 0.f);
        v.z += fmaxf(m2, 0.f); v.w += fmaxf(m3, 0.f);
        *(float4*)(g_x + base) = v;
    }
    float s = v.x + v.y + v.z + v.w;
    #pragma unroll
    for (int o = 16; o > 0; o >>= 1) s += __shfl_xor_sync(0xffffffffu, s, o);
    if ((t & 31) == 0) red[t >> 5] = s;
    __syncthreads();
    if (t == 0) red[4] = red[0] + red[1] + red[2] + red[3];
    __syncthreads();
    float mu = red[4] * (1.0f / D);
    __syncthreads();
    float dx = v.x - mu, dy = v.y - mu, dz = v.z - mu, dw = v.w - mu;
    float q = dx * dx + dy * dy + dz * dz + dw * dw;
    #pragma unroll
    for (int o = 16; o > 0; o >>= 1) q += __shfl_xor_sync(0xffffffffu, q, o);
    if ((t & 31) == 0) red[t >> 5] = q;
    __syncthreads();
    if (t == 0) red[4] = red[0] + red[1] + red[2] + red[3];
    __syncthreads();
    float rstd = rsqrtf(red[4] * (1.0f / D) + 1e-5f);
    float4 g4 = ((const float4*)gamma)[t];
    float4 b4 = ((const float4*)beta)[t];
    __half2 h0 = __floats2half2_rn(dx * rstd * g4.x + b4.x, dy * rstd * g4.y + b4.y);
    __half2 h1 = __floats2half2_rn(dz * rstd * g4.z + b4.z, dw * rstd * g4.w + b4.w);
    *(uint2*)(out + base) = make_uint2(*(uint32_t*)&h0, *(uint32_t*)&h1);
}

// selected-rows combine + LN2 -> compact fp16 + compact fp32 residual (agg read-only).
__global__ __launch_bounds__(128) void k_lnc_sel(const int* __restrict__ sel,
                                                 const float* __restrict__ b2,
                                                 const float* __restrict__ gamma,
                                                 const float* __restrict__ beta,
                                                 __half* __restrict__ hout) {
    __shared__ float red[8];
    int r = blockIdx.x;
    int t = threadIdx.x;
    int node = (r >> 7) * NPG + sel[r];
    size_t base = (size_t)node * D + t * 4;
    float4 v = *(const float4*)(g_x + base);
    uint4 u = *(const uint4*)(g_agg + base);
    float4 bv = ((const float4*)b2)[t];
    float m0 = u.x ? fdec(u.x) + bv.x : 0.f;
    float m1 = u.y ? fdec(u.y) + bv.y : 0.f;
    float m2 = u.z ? fdec(u.z) + bv.z : 0.f;
    float m3 = u.w ? fdec(u.w) + bv.w : 0.f;
    v.x += fmaxf(m0, 0.f); v.y += fmaxf(m1, 0.f);
    v.z += fmaxf(m2, 0.f); v.w += fmaxf(m3, 0.f);
    *(float4*)(g_res + (size_t)r * D + t * 4) = v;

    float s = v.x + v.y + v.z + v.w;
    #pragma unroll
    for (int o = 16; o > 0; o >>= 1) s += __shfl_xor_sync(0xffffffffu, s, o);
    if ((t & 31) == 0) red[t >> 5] = s;
    __syncthreads();
    if (t == 0) red[4] = red[0] + red[1] + red[2] + red[3];
    __syncthreads();
    float mu = red[4] * (1.0f / D);
    __syncthreads();
    float dx = v.x - mu, dy = v.y - mu, dz = v.z - mu, dw = v.w - mu;
    float q = dx * dx + dy * dy + dz * dz + dw * dw;
    #pragma unroll
    for (int o = 16; o > 0; o >>= 1) q += __shfl_xor_sync(0xffffffffu, q, o);
    if ((t & 31) == 0) red[t >> 5] = q;
    __syncthreads();
    if (t == 0) red[4] = red[0] + red[1] + red[2] + red[3];
    __syncthreads();
    float rstd = rsqrtf(red[4] * (1.0f / D) + 1e-5f);
    float4 g4 = ((const float4*)gamma)[t];
    float4 b4 = ((const float4*)beta)[t];
    __half2 h0 = __floats2half2_rn(dx * rstd * g4.x + b4.x, dy * rstd * g4.y + b4.y);
    __half2 h1 = __floats2half2_rn(dz * rstd * g4.z + b4.z, dw * rstd * g4.w + b4.w);
    *(uint2*)(hout + (size_t)r * D + t * 4) = make_uint2(*(uint32_t*)&h0, *(uint32_t*)&h1);
}

// Z build over an edge list (sorted, possibly filtered+padded)
__global__ __launch_bounds__(256) void k_zbuild(const int* __restrict__ eD,
                                                const int* __restrict__ eS,
                                                const int* __restrict__ dynCount) {
    int e = blockIdx.x * 8 + (threadIdx.x >> 5);
    if (dynCount && e >= *dynCount) return;
    int sg = threadIdx.x & 31;
    int de = eD[e], se = eS[e];
    const uint4* a = (const uint4*)(g_A16 + (size_t)de * D);
    const uint4* b = (const uint4*)(g_B16 + (size_t)se * D);
    uint4* z = (uint4*)(g_Z + (size_t)e * D);
    const __half2 zero2 = __floats2half2_rn(0.f, 0.f);
    #pragma unroll
    for (int i = 0; i < 2; i++) {
        int s = sg + i * 32;
        uint4 av = a[s], bv = b[s];
        uint4 r;
        __half2 h;
        h = __hmax2(__hadd2(*(__half2*)&av.x, *(__half2*)&bv.x), zero2); r.x = *(uint32_t*)&h;
        h = __hmax2(__hadd2(*(__half2*)&av.y, *(__half2*)&bv.y), zero2); r.y = *(uint32_t*)&h;
        h = __hmax2(__hadd2(*(__half2*)&av.z, *(__half2*)&bv.z), zero2); r.z = *(uint32_t*)&h;
        h = __hmax2(__hadd2(*(__half2*)&av.w, *(__half2*)&bv.w), zero2); r.w = *(uint32_t*)&h;
        z[s] = r;
    }
}

// ================= dense fp16 GEMM (generic) =================
__global__ __launch_bounds__(256, 2) void k_mma_gemm(
    const __half* __restrict__ Ain,
    const __half* __restrict__ w,
    const float* __restrict__ bias,
    const float* __restrict__ res,
    float* __restrict__ out,
    __half* __restrict__ out16,
    int relu)
{
    extern __shared__ char smem[];
    int tid = threadIdx.x;
    int n0 = blockIdx.x * BN;
    int m0 = blockIdx.y * BM;
    int lane = tid & 31, wm = (tid >> 5) & 1, wn = tid >> 6;

    uint32_t s[NSTG];
    #pragma unroll
    for (int i = 0; i < NSTG; i++) s[i] = smem_u32(smem + i * STAGE);
    const __half* abase = Ain + (size_t)m0 * D;
    const __half* wbase = w + (size_t)n0 * D;
    uint32_t aoff = (uint32_t)(wm * 64 + (lane & 7) + ((lane >> 3) & 1) * 8) * ROWB
                  + ((lane >> 4) & 1) * 16;
    uint32_t boff = (uint32_t)(wn * 32 + (lane & 7) + ((lane >= 16) ? 8 : 0)) * ROWB
                  + ((lane >> 3) & 1) * 16;

    float acc[4][4][4] = {};

    cp_rows128(s[0] + SA, abase, 0, tid);
    cp_rows128(s[0] + SW, wbase, 0, tid);
    cp_commit();
    cp_rows128(s[1] + SA, abase, BK, tid);
    cp_rows128(s[1] + SW, wbase, BK, tid);
    cp_commit();
    cp_wait<1>();
    __syncthreads();

    for (int c = 0; c < NCH; c++) {
        uint32_t sc = s[c % NSTG];
        if (c + 2 < NCH) {
            uint32_t sn = s[(c + 2) % NSTG];
            cp_rows128(sn + SA, abase, (c + 2) * BK, tid);
            cp_rows128(sn + SW, wbase, (c + 2) * BK, tid);
            cp_commit();
        }
        #pragma unroll
        for (int kh = 0; kh < 4; kh++) {
            uint32_t bh[2][4];
            #pragma unroll
            for (int np = 0; np < 2; np++)
                ldm_x4(bh[np], sc + SW + boff + np * 16 * ROWB + kh * 32);
            #pragma unroll
            for (int mf = 0; mf < 4; mf++) {
                uint32_t ah[4];
                ldm_x4(ah, sc + SA + aoff + mf * 16 * ROWB + kh * 32);
                #pragma unroll
                for (int np = 0; np < 2; np++) {
                    #pragma unroll
                    for (int j = 0; j < 2; j++)
                        mma_h(acc[mf][np * 2 + j], ah, bh[np][2 * j], bh[np][2 * j + 1]);
                }
            }
        }
        if (c + 2 < NCH) cp_wait<1>();
        else if (c + 1 < NCH) cp_wait<0>();
        __syncthreads();
    }

    #pragma unroll
    for (int mf = 0; mf < 4; mf++) {
        int r0 = m0 + wm * 64 + mf * 16 + (lane >> 2);
        int colb = n0 + wn * 32 + 2 * (lane & 3);
        #pragma unroll
        for (int nf = 0; nf < 4; nf++) {
            int col = colb + nf * 8;
            float2 bv = bias ? *(const float2*)(bias + col) : make_float2(0.f, 0.f);
            float c0 = acc[mf][nf][0] + bv.x, c1 = acc[mf][nf][1] + bv.y;
            float c2 = acc[mf][nf][2] + bv.x, c3 = acc[mf][nf][3] + bv.y;
            if (relu) {
                c0 = fmaxf(c0, 0.f); c1 = fmaxf(c1, 0.f);
                c2 = fmaxf(c2, 0.f); c3 = fmaxf(c3, 0.f);
            }
            if (res) {
                float2 r1v = *(const float2*)(res + (size_t)r0 * D + col);
                float2 r2v = *(const float2*)(res + (size_t)(r0 + 8) * D + col);
                c0 += r1v.x; c1 += r1v.y; c2 += r2v.x; c3 += r2v.y;
            }
            if (out) {
                *(float2*)(out + (size_t)r0 * D + col) = make_float2(c0, c1);
                *(float2*)(out + (size_t)(r0 + 8) * D + col) = make_float2(c2, c3);
            }
            if (out16) {
                __half2 h0 = __floats2half2_rn(c0, c1);
                __half2 h1 = __floats2half2_rn(c2, c3);
                *(uint32_t*)(out16 + (size_t)r0 * D + col) = *(uint32_t*)&h0;
                *(uint32_t*)(out16 + (size_t)(r0 + 8) * D + col) = *(uint32_t*)&h1;
            }
        }
    }
}

// ================= merged A|B node GEMM =================
__global__ __launch_bounds__(256, 2) void k_mma_ab(
    const __half* __restrict__ Hm,
    const __half* __restrict__ w,
    const float* __restrict__ b1,
    __half* __restrict__ A16,
    __half* __restrict__ B16)
{
    extern __shared__ char smem[];
    int tid = threadIdx.x;
    int n0 = blockIdx.x * BN;
    int m0 = blockIdx.y * BM;
    int lane = tid & 31, wm = (tid >> 5) & 1, wn = tid >> 6;

    bool isA = (n0 < D);
    __half* dstbuf = isA ? A16 : B16;
    int cbase = isA ? 0 : D;
    const float* bias = isA ? b1 : nullptr;

    uint32_t s[NSTG];
    #pragma unroll
    for (int i = 0; i < NSTG; i++) s[i] = smem_u32(smem + i * STAGE);
    const __half* abase = Hm + (size_t)m0 * D;
    const __half* wbase = w + (size_t)n0 * D;
    uint32_t aoff = (uint32_t)(wm * 64 + (lane & 7) + ((lane >> 3) & 1) * 8) * ROWB
                  + ((lane >> 4) & 1) * 16;
    uint32_t boff = (uint32_t)(wn * 32 + (lane & 7) + ((lane >= 16) ? 8 : 0)) * ROWB
                  + ((lane >> 3) & 1) * 16;

    float acc[4][4][4] = {};

    cp_rows128(s[0] + SA, abase, 0, tid);
    cp_rows128(s[0] + SW, wbase, 0, tid);
    cp_commit();
    cp_rows128(s[1] + SA, abase, BK, tid);
    cp_rows128(s[1] + SW, wbase, BK, tid);
    cp_commit();
    cp_wait<1>();
    __syncthreads();

    for (int c = 0; c < NCH; c++) {
        uint32_t sc = s[c % NSTG];
        if (c + 2 < NCH) {
            uint32_t sn = s[(c + 2) % NSTG];
            cp_rows128(sn + SA, abase, (c + 2) * BK, tid);
            cp_rows128(sn + SW, wbase, (c + 2) * BK, tid);
            cp_commit();
        }
        #pragma unroll
        for (int kh = 0; kh < 4; kh++) {
            uint32_t bh[2][4];
            #pragma unroll
            for (int np = 0; np < 2; np++)
                ldm_x4(bh[np], sc + SW + boff + np * 16 * ROWB + kh * 32);
            #pragma unroll
            for (int mf = 0; mf < 4; mf++) {
                uint32_t ah[4];
                ldm_x4(ah, sc + SA + aoff + mf * 16 * ROWB + kh * 32);
                #pragma unroll
                for (int np = 0; np < 2; np++) {
                    #pragma unroll
                    for (int j = 0; j < 2; j++)
                        mma_h(acc[mf][np * 2 + j], ah, bh[np][2 * j], bh[np][2 * j + 1]);
                }
            }
        }
        if (c + 2 < NCH) cp_wait<1>();
        else if (c + 1 < NCH) cp_wait<0>();
        __syncthreads();
    }

    #pragma unroll
    for (int mf = 0; mf < 4; mf++) {
        int r0 = m0 + wm * 64 + mf * 16 + (lane >> 2);
        int colb = n0 + wn * 32 + 2 * (lane & 3);
        #pragma unroll
        for (int nf = 0; nf < 4; nf++) {
            int col = colb + nf * 8;
            float2 bv = bias ? *(const float2*)(bias + col) : make_float2(0.f, 0.f);
            float c0 = acc[mf][nf][0] + bv.x, c1 = acc[mf][nf][1] + bv.y;
            float c2 = acc[mf][nf][2] + bv.x, c3 = acc[mf][nf][3] + bv.y;
            int dc = col - cbase;
            __half2 h0 = __floats2half2_rn(c0, c1);
            __half2 h1 = __floats2half2_rn(c2, c3);
            *(uint32_t*)(dstbuf + (size_t)r0 * D + dc) = *(uint32_t*)&h0;
            *(uint32_t*)(dstbuf + (size_t)(r0 + 8) * D + dc) = *(uint32_t*)&h1;
        }
    }
}

// ================= edge GEMM: Z(sorted list) @ W2 -> smem segment-reduce -> atomicMax =================
__global__ __launch_bounds__(256, 2) void k_mma_edge(
    const __half* __restrict__ w16,
    const float* __restrict__ b2,
    unsigned* __restrict__ agg,
    const int* __restrict__ eD,
    const int* __restrict__ tileLimit)
{
    extern __shared__ char smem[];
    int e0 = blockIdx.y * BM;
    if (tileLimit && blockIdx.y >= *tileLimit) return;
    int tid = threadIdx.x;
    int n0 = blockIdx.x * BN;
    int lane = tid & 31, wm = (tid >> 5) & 1, wn = tid >> 6;

    int* sDst = (int*)(smem + SM_IDX);
    if (tid < 128) sDst[tid] = eD[e0 + tid];

    uint32_t s[NSTG];
    #pragma unroll
    for (int i = 0; i < NSTG; i++) s[i] = smem_u32(smem + i * STAGE);
    const __half* abase = g_Z + (size_t)e0 * D;
    const __half* wbase = w16 + (size_t)n0 * D;
    uint32_t aoff = (uint32_t)(wm * 64 + (lane & 7) + ((lane >> 3) & 1) * 8) * ROWB
                  + ((lane >> 4) & 1) * 16;
    uint32_t boff = (uint32_t)(wn * 32 + (lane & 7) + ((lane >= 16) ? 8 : 0)) * ROWB
                  + ((lane >> 3) & 1) * 16;

    float acc[4][4][4] = {};

    cp_rows128(s[0] + SA, abase, 0, tid);
    cp_rows128(s[0] + SW, wbase, 0, tid);
    cp_commit();
    cp_rows128(s[1] + SA, abase, BK, tid);
    cp_rows128(s[1] + SW, wbase, BK, tid);
    cp_commit();
    cp_wait<1>();
    __syncthreads();

    for (int c = 0; c < NCH; c++) {
        uint32_t sc = s[c % NSTG];
        if (c + 2 < NCH) {
            uint32_t sn = s[(c + 2) % NSTG];
            cp_rows128(sn + SA, abase, (c + 2) * BK, tid);
            cp_rows128(sn + SW, wbase, (c + 2) * BK, tid);
            cp_commit();
        }
        #pragma unroll
        for (int kh = 0; kh < 4; kh++) {
            uint32_t bh[2][4];
            #pragma unroll
            for (int np = 0; np < 2; np++)
                ldm_x4(bh[np], sc + SW + boff + np * 16 * ROWB + kh * 32);
            #pragma unroll
            for (int mf = 0; mf < 4; mf++) {
                uint32_t ah[4];
                ldm_x4(ah, sc + SA + aoff + mf * 16 * ROWB + kh * 32);
                #pragma unroll
                for (int np = 0; np < 2; np++) {
                    #pragma unroll
                    for (int j = 0; j < 2; j++)
                        mma_h(acc[mf][np * 2 + j], ah, bh[np][2 * j], bh[np][2 * j + 1]);
                }
            }
        }
        if (c + 2 < NCH) cp_wait<1>();
        else if (c + 1 < NCH) cp_wait<0>();
        __syncthreads();
    }

    // epilogue: acc -> smem f32 tile, segment-reduce by sorted dst, gated atomics
    float* T = (float*)smem;
    #pragma unroll
    for (int mf = 0; mf < 4; mf++) {
        int r0 = wm * 64 + mf * 16 + (lane >> 2);
        int cl = wn * 32 + 2 * (lane & 3);
        #pragma unroll
        for (int nf = 0; nf < 4; nf++) {
            *(float2*)&T[r0 * TPAD + cl + nf * 8] =
                make_float2(acc[mf][nf][0], acc[mf][nf][1]);
            *(float2*)&T[(r0 + 8) * TPAD + cl + nf * 8] =
                make_float2(acc[mf][nf][2], acc[mf][nf][3]);
        }
    }
    __syncthreads();

    {
        int col = tid & 127, half = tid >> 7;
        float thr = -b2[n0 + col];
        unsigned* aggcol = agg + n0 + col;
        int rbeg = half * 64, rend = rbeg + 64;
        int prevd = sDst[rbeg];
        float run = -FLT_MAX;
        for (int r = rbeg; r < rend; r++) {
            int d = sDst[r];
            float v = T[r * TPAD + col];
            if (d != prevd) {
                if (run > thr) atomicMax(aggcol + (size_t)prevd * D, fenc(run));
                prevd = d;
                run = v;
            } else {
                run = fmaxf(run, v);
            }
        }
        if (run > thr) atomicMax(aggcol + (size_t)prevd * D, fenc(run));
    }
}

// ================= host launcher =================
extern "C" void kernel_launch(void* const* d_in, const int* in_sizes, int n_in,
                              void* d_out, int out_size) {
    const float* x       = (const float*)d_in[0];
    const int*   eidx    = (const int*)d_in[1];
    const int*   sel     = (const int*)d_in[2];
    const float* conv_W1 = (const float*)d_in[4];
    const float* conv_b1 = (const float*)d_in[5];
    const float* conv_W2 = (const float*)d_in[6];
    const float* conv_b2 = (const float*)d_in[7];
    const float* ln1_g   = (const float*)d_in[8];
    const float* ln1_b   = (const float*)d_in[9];
    const float* ln2_g   = (const float*)d_in[10];
    const float* ln2_b   = (const float*)d_in[11];
    const float* ffn_W1  = (const float*)d_in[12];
    const float* ffn_b1  = (const float*)d_in[13];
    const float* ffn_W2  = (const float*)d_in[14];
    const float* ffn_b2  = (const float*)d_in[15];
    float* out = (float*)d_out;

    const int* src = eidx;
    const int* dst = eidx + E_EDGES;

    float *gres;
    unsigned* gagg;
    __half *gh16, *gt16, *ga16, *gb16, *gw16;
    int *geD, *geD3, *geS, *geS3, *gpadE3, *gtiles3;
    cudaGetSymbolAddress((void**)&gres, g_res);
    cudaGetSymbolAddress((void**)&gagg, g_agg);
    cudaGetSymbolAddress((void**)&gh16, g_h16);
    cudaGetSymbolAddress((void**)&gt16, g_t16);
    cudaGetSymbolAddress((void**)&ga16, g_A16);
    cudaGetSymbolAddress((void**)&gb16, g_B16);
    cudaGetSymbolAddress((void**)&gw16, g_W16);
    cudaGetSymbolAddress((void**)&geD, g_eDst);
    cudaGetSymbolAddress((void**)&geD3, g_eDst3);
    cudaGetSymbolAddress((void**)&geS, g_eSrc);
    cudaGetSymbolAddress((void**)&geS3, g_eSrc3);
    cudaGetSymbolAddress((void**)&gpadE3, g_padE3);
    cudaGetSymbolAddress((void**)&gtiles3, g_tiles3);

    cudaFuncSetAttribute(k_mma_gemm, cudaFuncAttributeMaxDynamicSharedMemorySize, SMEM_GEMM);
    cudaFuncSetAttribute(k_mma_ab,   cudaFuncAttributeMaxDynamicSharedMemorySize, SMEM_GEMM);
    cudaFuncSetAttribute(k_mma_edge, cudaFuncAttributeMaxDynamicSharedMemorySize, SMEM_EDGE);

    auto W = [&](int m) { return gw16 + (size_t)m * D * D; };

    const int ND = N_NODES * D;

    k_init<<<ND / 256, 256>>>();
    k_mask<<<NSEL / 256, 256>>>(sel);
    k_hist<<<E_EDGES / 256, 256>>>(dst);
    {
        dim3 grid(16, 16, NMAT);
        k_prep16t<<<grid, 256>>>(conv_W1, conv_W2, ffn_W1, ffn_W2, gw16);
    }
    k_scan2<<<1, 1024>>>();
    k_scatter<<<E_EDGES / 256, 256>>>(src, dst);
    k_pad<<<1, 256>>>();

    dim3 gffn(D / BN, NSEL / BM);            // (4, 16)
    dim3 gab(2 * D / BN, N_NODES / BM);      // (8, 64)
    dim3 gedge(D / BN, E_EDGES / BM);        // (4, 1024)

    for (int l = 0; l < L_LAYERS; l++) {
        if (l == 0)
            k_lnc<<<N_NODES, 128>>>(x, 0, conv_b2, ln1_g, ln1_b, gh16);
        else
            k_lnc<<<N_NODES, 128>>>(nullptr, 1, conv_b2 + (size_t)(l - 1) * D,
                                    ln1_g, ln1_b, gh16);
        k_mma_ab<<<gab, 256, SMEM_GEMM>>>(gh16, W(l * 3 + 0),
                                          conv_b1 + (size_t)l * D, ga16, gb16);
        if (l < 2) {
            k_zbuild<<<E_EDGES / 8, 256>>>(geD, geS, nullptr);
            k_mma_edge<<<gedge, 256, SMEM_EDGE>>>(W(l * 3 + 2),
                                                  conv_b2 + (size_t)l * D, gagg,
                                                  geD, nullptr);
        } else {
            k_zbuild<<<E_EDGES / 8, 256>>>(geD3, geS3, gpadE3);
            k_mma_edge<<<gedge, 256, SMEM_EDGE>>>(W(l * 3 + 2),
                                                  conv_b2 + (size_t)l * D, gagg,
                                                  geD3, gtiles3);
        }
    }

    // selected-rows tail: combine layer-3 agg + LN2 (compact), FFN, write d_out
    k_lnc_sel<<<NSEL, 128>>>(sel, conv_b2 + (size_t)2 * D, ln2_g, ln2_b, gh16);
    k_mma_gemm<<<gffn, 256, SMEM_GEMM>>>(gh16, W(9), ffn_b1, nullptr,
                                         nullptr, gt16, 1);
    k_mma_gemm<<<gffn, 256, SMEM_GEMM>>>(gt16, W(10), ffn_b2, gres,
                                         out, nullptr, 0);
}